// round 12
// baseline (speedup 1.0000x reference)
#include <cuda_runtime.h>
#include <math.h>
#include <stdint.h>

#define NL  8
#define D   1024
#define NH  16
#define VOC 32000
#define TT  1024
#define BB  2
#define HDIM 64
#define MM  2048   // B*T

// ---------------- scratch (device globals; no allocations allowed) ----------
static __device__ float g_X  [(size_t)MM * D];
static __device__ float g_Hb [(size_t)MM * D];
static __device__ float g_QKV[(size_t)MM * 3 * D];
static __device__ float g_Y  [(size_t)MM * D];
static __device__ float g_FF [(size_t)MM * 4 * D];
static __device__ float g_NLL[(size_t)MM];

// ---------------- helpers -----------------------------------------------------
__device__ __forceinline__ uint32_t f2tf(float f) {
    uint32_t r;
    asm("cvt.rna.tf32.f32 %0, %1;" : "=r"(r) : "f"(f));
    return r;
}

__device__ __forceinline__ float blk_sum(float v, float* sh) {
    #pragma unroll
    for (int o = 16; o; o >>= 1) v += __shfl_xor_sync(0xffffffffu, v, o);
    if ((threadIdx.x & 31) == 0) sh[threadIdx.x >> 5] = v;
    __syncthreads();
    float r = 0.f;
    #pragma unroll
    for (int i = 0; i < 8; i++) r += sh[i];
    __syncthreads();
    return r;
}

__device__ __forceinline__ float blk_max(float v, float* sh) {
    #pragma unroll
    for (int o = 16; o; o >>= 1) v = fmaxf(v, __shfl_xor_sync(0xffffffffu, v, o));
    if ((threadIdx.x & 31) == 0) sh[threadIdx.x >> 5] = v;
    __syncthreads();
    float r = -1e30f;
    #pragma unroll
    for (int i = 0; i < 8; i++) r = fmaxf(r, sh[i]);
    __syncthreads();
    return r;
}

// ---------------- embedding --------------------------------------------------
__global__ void embed_k(const int* __restrict__ idx, const float* __restrict__ tok,
                        const float* __restrict__ pos, float* __restrict__ X) {
    const int r = blockIdx.x;
    const int t = r & (TT - 1);
    const int id = idx[r];
    const float* te = tok + (size_t)id * D;
    const float* pe = pos + (size_t)t * D;
    float* xr = X + (size_t)r * D;
    for (int c = threadIdx.x; c < D; c += 256)
        xr[c] = te[c] + pe[c];
}

// ---------------- layernorm: one warp per row, shfl-only ----------------------
__global__ void __launch_bounds__(256) ln_w_k(const float* __restrict__ X,
                                              const float* __restrict__ s,
                                              const float* __restrict__ b,
                                              float* __restrict__ O) {
    const int warp = threadIdx.x >> 5, lane = threadIdx.x & 31;
    const int r = (blockIdx.x << 3) + warp;
    const float* xr = X + (size_t)r * D;
    float4 xv[8];
    float sum = 0.f;
    #pragma unroll
    for (int j = 0; j < 8; j++) {
        xv[j] = *(const float4*)&xr[(j * 32 + lane) << 2];
        sum += xv[j].x + xv[j].y + xv[j].z + xv[j].w;
    }
    #pragma unroll
    for (int o = 16; o; o >>= 1) sum += __shfl_xor_sync(0xffffffffu, sum, o);
    const float mean = sum * (1.f / D);
    float var = 0.f;
    #pragma unroll
    for (int j = 0; j < 8; j++) {
        xv[j].x -= mean; xv[j].y -= mean; xv[j].z -= mean; xv[j].w -= mean;
        var += xv[j].x * xv[j].x + xv[j].y * xv[j].y
             + xv[j].z * xv[j].z + xv[j].w * xv[j].w;
    }
    #pragma unroll
    for (int o = 16; o; o >>= 1) var += __shfl_xor_sync(0xffffffffu, var, o);
    const float rinv = rsqrtf(var * (1.f / D) + 1e-5f);
    float* orow = O + (size_t)r * D;
    #pragma unroll
    for (int j = 0; j < 8; j++) {
        const int c = (j * 32 + lane) << 2;
        const float4 sv = *(const float4*)&s[c];
        const float4 bv = *(const float4*)&b[c];
        float4 o;
        o.x = xv[j].x * rinv * sv.x + bv.x;
        o.y = xv[j].y * rinv * sv.y + bv.y;
        o.z = xv[j].z * rinv * sv.z + bv.z;
        o.w = xv[j].w * rinv * sv.w + bv.w;
        *(float4*)&orow[c] = o;
    }
}

// ---------------- TF32 MMA macro ----------------------------------------------
#define MMA_TF32(d, a, b)                                                        \
    asm volatile(                                                                \
        "mma.sync.aligned.m16n8k8.row.col.f32.tf32.tf32.f32 "                    \
        "{%0,%1,%2,%3},{%4,%5,%6,%7},{%8,%9},{%0,%1,%2,%3};\n"                   \
        : "+f"(d[0]), "+f"(d[1]), "+f"(d[2]), "+f"(d[3])                         \
        : "r"(a[0]), "r"(a[1]), "r"(a[2]), "r"(a[3]), "r"(b[0]), "r"(b[1]))

// ---------------- TF32 tensor-core GEMM (double-buffered, 2 CTAs/SM) -----------
template<int DO_BIAS, int DO_GELU, int DO_RES, int SWAP>
__global__ void __launch_bounds__(256, 2) gemm_tf32_k(
    const float* __restrict__ A, const float* __restrict__ W,
    const float* __restrict__ bias, const float* __restrict__ res,
    float* __restrict__ C, int M, int N, int K)
{
    __shared__ uint32_t As[2][128][20];
    __shared__ uint32_t Bs[2][16][136];
    const int bm = (SWAP ? blockIdx.x : blockIdx.y) << 7;
    const int bn = (SWAP ? blockIdx.y : blockIdx.x) << 7;
    const int tid = threadIdx.x;
    const int warp = tid >> 5, lane = tid & 31;
    const int g = lane >> 2, t4 = lane & 3;
    const int wm = (warp >> 2) << 6;
    const int wn = (warp & 3) << 5;

    float acc[4][4][4];
    #pragma unroll
    for (int i = 0; i < 4; i++)
        #pragma unroll
        for (int j = 0; j < 4; j++)
            #pragma unroll
            for (int h = 0; h < 4; h++) acc[i][j][h] = 0.f;

    int a_r[2], a_c[2], b_r[2], b_c[2];
    #pragma unroll
    for (int i = 0; i < 2; i++) {
        const int idx = tid + (i << 8);
        a_r[i] = idx >> 2;  a_c[i] = (idx & 3) << 2;
        b_r[i] = idx >> 5;  b_c[i] = (idx & 31) << 2;
    }

    float4 pa[2], pb[2];
    #pragma unroll
    for (int i = 0; i < 2; i++) {
        pa[i] = *(const float4*)&A[(size_t)(bm + a_r[i]) * K + a_c[i]];
        pb[i] = *(const float4*)&W[(size_t)b_r[i] * N + bn + b_c[i]];
    }

    const int ntiles = K >> 4;
    for (int kt = 0; kt < ntiles; kt++) {
        const int buf = kt & 1;
        #pragma unroll
        for (int i = 0; i < 2; i++) {
            As[buf][a_r[i]][a_c[i] + 0] = f2tf(pa[i].x);
            As[buf][a_r[i]][a_c[i] + 1] = f2tf(pa[i].y);
            As[buf][a_r[i]][a_c[i] + 2] = f2tf(pa[i].z);
            As[buf][a_r[i]][a_c[i] + 3] = f2tf(pa[i].w);
            uint4 bw;
            bw.x = f2tf(pb[i].x); bw.y = f2tf(pb[i].y);
            bw.z = f2tf(pb[i].z); bw.w = f2tf(pb[i].w);
            *(uint4*)&Bs[buf][b_r[i]][b_c[i]] = bw;
        }
        __syncthreads();

        if (kt + 1 < ntiles) {
            const int k0 = (kt + 1) << 4;
            #pragma unroll
            for (int i = 0; i < 2; i++) {
                pa[i] = *(const float4*)&A[(size_t)(bm + a_r[i]) * K + k0 + a_c[i]];
                pb[i] = *(const float4*)&W[(size_t)(k0 + b_r[i]) * N + bn + b_c[i]];
            }
        }

        #pragma unroll
        for (int ks = 0; ks < 2; ks++) {
            const int kb = ks << 3;
            uint32_t af[4][4], bf[4][2];
            #pragma unroll
            for (int mt = 0; mt < 4; mt++) {
                const int m = wm + (mt << 4) + g;
                af[mt][0] = As[buf][m    ][kb + t4];
                af[mt][1] = As[buf][m + 8][kb + t4];
                af[mt][2] = As[buf][m    ][kb + t4 + 4];
                af[mt][3] = As[buf][m + 8][kb + t4 + 4];
            }
            #pragma unroll
            for (int nt = 0; nt < 4; nt++) {
                const int n = wn + (nt << 3) + g;
                bf[nt][0] = Bs[buf][kb + t4    ][n];
                bf[nt][1] = Bs[buf][kb + t4 + 4][n];
            }
            #pragma unroll
            for (int mt = 0; mt < 4; mt++)
                #pragma unroll
                for (int nt = 0; nt < 4; nt++)
                    MMA_TF32(acc[mt][nt], af[mt], bf[nt]);
        }
    }

    #pragma unroll
    for (int mt = 0; mt < 4; mt++) {
        #pragma unroll
        for (int nt = 0; nt < 4; nt++) {
            const int col = bn + wn + (nt << 3) + (t4 << 1);
            const float b0 = DO_BIAS ? bias[col]     : 0.f;
            const float b1 = DO_BIAS ? bias[col + 1] : 0.f;
            #pragma unroll
            for (int h = 0; h < 2; h++) {
                const int row = bm + wm + (mt << 4) + g + (h << 3);
                float v0 = acc[mt][nt][h * 2 + 0] + b0;
                float v1 = acc[mt][nt][h * 2 + 1] + b1;
                if (DO_GELU) {
                    v0 = 0.5f * v0 * (1.f + erff(v0 * 0.70710678118f));
                    v1 = 0.5f * v1 * (1.f + erff(v1 * 0.70710678118f));
                }
                const size_t off = (size_t)row * N + col;
                if (DO_RES) {
                    const float2 r = *(const float2*)&res[off];
                    v0 += r.x; v1 += r.y;
                }
                *(float2*)&C[off] = make_float2(v0, v1);
            }
        }
    }
}

// ---------------- fused flash attention (K/V register prefetch) ----------------
#define FLASH_SMEM (4 * 64 * 68 * 4 + 3 * 64 * 4)
__global__ void __launch_bounds__(256) attn_flash_k(const float* __restrict__ QKV,
                                                    float* __restrict__ Y) {
    extern __shared__ uint32_t dsm[];
    uint32_t (*Qs)[68] = (uint32_t(*)[68])dsm;
    uint32_t (*Ks)[68] = (uint32_t(*)[68])(dsm + 64 * 68);
    uint32_t (*Vs)[68] = (uint32_t(*)[68])(dsm + 2 * 64 * 68);
    uint32_t (*Ss)[68] = (uint32_t(*)[68])(dsm + 3 * 64 * 68);
    float* row_m     = (float*)(dsm + 4 * 64 * 68);
    float* row_l     = row_m + 64;
    float* row_scale = row_l + 64;

    const int q0 = blockIdx.x << 6;
    const int bh = blockIdx.y;
    const int b = bh >> 4, h = bh & 15;
    const int tid = threadIdx.x;
    const int warp = tid >> 5, lane = tid & 31;
    const int g = lane >> 2, t4 = lane & 3;
    const int wm = (warp >> 2) << 5;
    const int wn = (warp & 3) << 4;

    if (tid < 64) { row_m[tid] = -1e30f; row_l[tid] = 0.f; }

    int ld_r[4], ld_c[4];
    #pragma unroll
    for (int i = 0; i < 4; i++) {
        const int idx = tid + (i << 8);
        ld_r[i] = idx >> 4;
        ld_c[i] = (idx & 15) << 2;
    }

    #pragma unroll
    for (int i = 0; i < 4; i++) {
        const float4 qv = *(const float4*)&QKV[(size_t)(b * TT + q0 + ld_r[i]) * (3 * D) + h * HDIM + ld_c[i]];
        Qs[ld_r[i]][ld_c[i] + 0] = f2tf(qv.x); Qs[ld_r[i]][ld_c[i] + 1] = f2tf(qv.y);
        Qs[ld_r[i]][ld_c[i] + 2] = f2tf(qv.z); Qs[ld_r[i]][ld_c[i] + 3] = f2tf(qv.w);
    }

    float4 pk[4], pv[4];
    #pragma unroll
    for (int i = 0; i < 4; i++) {
        pk[i] = *(const float4*)&QKV[(size_t)(b * TT + ld_r[i]) * (3 * D) + D + h * HDIM + ld_c[i]];
        pv[i] = *(const float4*)&QKV[(size_t)(b * TT + ld_r[i]) * (3 * D) + 2 * D + h * HDIM + ld_c[i]];
    }

    float oacc[2][2][4];
    #pragma unroll
    for (int i = 0; i < 2; i++)
        #pragma unroll
        for (int j = 0; j < 2; j++)
            #pragma unroll
            for (int t = 0; t < 4; t++) oacc[i][j][t] = 0.f;

    for (int kt = 0; kt < 16; kt++) {
        #pragma unroll
        for (int i = 0; i < 4; i++) {
            Ks[ld_r[i]][ld_c[i] + 0] = f2tf(pk[i].x); Ks[ld_r[i]][ld_c[i] + 1] = f2tf(pk[i].y);
            Ks[ld_r[i]][ld_c[i] + 2] = f2tf(pk[i].z); Ks[ld_r[i]][ld_c[i] + 3] = f2tf(pk[i].w);
            Vs[ld_r[i]][ld_c[i] + 0] = f2tf(pv[i].x); Vs[ld_r[i]][ld_c[i] + 1] = f2tf(pv[i].y);
            Vs[ld_r[i]][ld_c[i] + 2] = f2tf(pv[i].z); Vs[ld_r[i]][ld_c[i] + 3] = f2tf(pv[i].w);
        }
        __syncthreads();

        if (kt + 1 < 16) {
            const int kn = (kt + 1) << 6;
            #pragma unroll
            for (int i = 0; i < 4; i++) {
                pk[i] = *(const float4*)&QKV[(size_t)(b * TT + kn + ld_r[i]) * (3 * D) + D + h * HDIM + ld_c[i]];
                pv[i] = *(const float4*)&QKV[(size_t)(b * TT + kn + ld_r[i]) * (3 * D) + 2 * D + h * HDIM + ld_c[i]];
            }
        }

        float sacc[2][2][4];
        #pragma unroll
        for (int i = 0; i < 2; i++)
            #pragma unroll
            for (int j = 0; j < 2; j++)
                #pragma unroll
                for (int t = 0; t < 4; t++) sacc[i][j][t] = 0.f;
        #pragma unroll
        for (int kb = 0; kb < 64; kb += 8) {
            uint32_t af[2][4], bf[2][2];
            #pragma unroll
            for (int mt = 0; mt < 2; mt++) {
                const int m = wm + (mt << 4) + g;
                af[mt][0] = Qs[m    ][kb + t4];
                af[mt][1] = Qs[m + 8][kb + t4];
                af[mt][2] = Qs[m    ][kb + t4 + 4];
                af[mt][3] = Qs[m + 8][kb + t4 + 4];
            }
            #pragma unroll
            for (int nt = 0; nt < 2; nt++) {
                const int n = wn + (nt << 3) + g;
                bf[nt][0] = Ks[n][kb + t4];
                bf[nt][1] = Ks[n][kb + t4 + 4];
            }
            #pragma unroll
            for (int mt = 0; mt < 2; mt++)
                #pragma unroll
                for (int nt = 0; nt < 2; nt++)
                    MMA_TF32(sacc[mt][nt], af[mt], bf[nt]);
        }
        #pragma unroll
        for (int mt = 0; mt < 2; mt++)
            #pragma unroll
            for (int nt = 0; nt < 2; nt++) {
                const int col = wn + (nt << 3) + (t4 << 1);
                #pragma unroll
                for (int hh = 0; hh < 2; hh++) {
                    const int row = wm + (mt << 4) + g + (hh << 3);
                    *(float2*)&Ss[row][col] = make_float2(sacc[mt][nt][hh * 2 + 0] * 0.125f,
                                                          sacc[mt][nt][hh * 2 + 1] * 0.125f);
                }
            }
        __syncthreads();

        {
            const int srow = tid >> 2, sq = tid & 3;
            float4 sv[4];
            float tmax = -1e30f;
            #pragma unroll
            for (int jj = 0; jj < 4; jj++) {
                sv[jj] = *(float4*)&Ss[srow][(sq << 4) + (jj << 2)];
                tmax = fmaxf(tmax, fmaxf(fmaxf(sv[jj].x, sv[jj].y), fmaxf(sv[jj].z, sv[jj].w)));
            }
            tmax = fmaxf(tmax, __shfl_xor_sync(0xffffffffu, tmax, 1));
            tmax = fmaxf(tmax, __shfl_xor_sync(0xffffffffu, tmax, 2));
            const float mo = row_m[srow];
            const float mn = fmaxf(mo, tmax);
            float tsum = 0.f;
            #pragma unroll
            for (int jj = 0; jj < 4; jj++) {
                sv[jj].x = __expf(sv[jj].x - mn); sv[jj].y = __expf(sv[jj].y - mn);
                sv[jj].z = __expf(sv[jj].z - mn); sv[jj].w = __expf(sv[jj].w - mn);
                tsum += sv[jj].x + sv[jj].y + sv[jj].z + sv[jj].w;
                uint4 u;
                u.x = f2tf(sv[jj].x); u.y = f2tf(sv[jj].y);
                u.z = f2tf(sv[jj].z); u.w = f2tf(sv[jj].w);
                *(uint4*)&Ss[srow][(sq << 4) + (jj << 2)] = u;
            }
            tsum += __shfl_xor_sync(0xffffffffu, tsum, 1);
            tsum += __shfl_xor_sync(0xffffffffu, tsum, 2);
            if (sq == 0) {
                const float sc = __expf(mo - mn);
                row_scale[srow] = sc;
                row_m[srow] = mn;
                row_l[srow] = row_l[srow] * sc + tsum;
            }
        }
        __syncthreads();

        #pragma unroll
        for (int mt = 0; mt < 2; mt++) {
            const float s0 = row_scale[wm + (mt << 4) + g];
            const float s1 = row_scale[wm + (mt << 4) + g + 8];
            #pragma unroll
            for (int nt = 0; nt < 2; nt++) {
                oacc[mt][nt][0] *= s0; oacc[mt][nt][1] *= s0;
                oacc[mt][nt][2] *= s1; oacc[mt][nt][3] *= s1;
            }
        }
        #pragma unroll
        for (int kb = 0; kb < 64; kb += 8) {
            uint32_t af[2][4], bf[2][2];
            #pragma unroll
            for (int mt = 0; mt < 2; mt++) {
                const int m = wm + (mt << 4) + g;
                af[mt][0] = Ss[m    ][kb + t4];
                af[mt][1] = Ss[m + 8][kb + t4];
                af[mt][2] = Ss[m    ][kb + t4 + 4];
                af[mt][3] = Ss[m + 8][kb + t4 + 4];
            }
            #pragma unroll
            for (int nt = 0; nt < 2; nt++) {
                const int n = wn + (nt << 3) + g;
                bf[nt][0] = Vs[kb + t4    ][n];
                bf[nt][1] = Vs[kb + t4 + 4][n];
            }
            #pragma unroll
            for (int mt = 0; mt < 2; mt++)
                #pragma unroll
                for (int nt = 0; nt < 2; nt++)
                    MMA_TF32(oacc[mt][nt], af[mt], bf[nt]);
        }
        __syncthreads();
    }

    #pragma unroll
    for (int mt = 0; mt < 2; mt++) {
        const float inv0 = 1.f / row_l[wm + (mt << 4) + g];
        const float inv1 = 1.f / row_l[wm + (mt << 4) + g + 8];
        #pragma unroll
        for (int nt = 0; nt < 2; nt++) {
            const int col = wn + (nt << 3) + (t4 << 1);
            const int row0 = q0 + wm + (mt << 4) + g;
            *(float2*)&Y[(size_t)(b * TT + row0) * D + h * HDIM + col] =
                make_float2(oacc[mt][nt][0] * inv0, oacc[mt][nt][1] * inv0);
            *(float2*)&Y[(size_t)(b * TT + row0 + 8) * D + h * HDIM + col] =
                make_float2(oacc[mt][nt][2] * inv1, oacc[mt][nt][3] * inv1);
        }
    }
}

// ---------------- loss ----------------------------------------------------------
__global__ void __launch_bounds__(256) nll_k(const float* __restrict__ logits,
                                             const int* __restrict__ tgt,
                                             float* __restrict__ nll) {
    __shared__ float sh[8];
    const int r = blockIdx.x;
    const float* row = logits + (size_t)r * VOC;
    float m = -1e30f;
    for (int c = threadIdx.x; c < VOC; c += 256) m = fmaxf(m, row[c]);
    m = blk_max(m, sh);
    float s = 0.f;
    for (int c = threadIdx.x; c < VOC; c += 256) s += __expf(row[c] - m);
    s = blk_sum(s, sh);
    if (threadIdx.x == 0) nll[r] = m + logf(s) - row[tgt[r]];
}

__global__ void __launch_bounds__(256) loss_k(const float* __restrict__ nll,
                                              float* __restrict__ out) {
    __shared__ float sh[8];
    float s = 0.f;
    for (int i = threadIdx.x; i < MM; i += 256) s += nll[i];
    s = blk_sum(s, sh);
    if (threadIdx.x == 0) out[0] = s * (1.f / MM);
}

// ---------------- orchestration --------------------------------------------------
extern "C" void kernel_launch(void* const* d_in, const int* in_sizes, int n_in,
                              void* d_out, int out_size) {
    const int*   idx     = (const int*)  d_in[0];
    const int*   targets = (const int*)  d_in[1];
    const float* tok_emb = (const float*)d_in[2];
    const float* pos_emb = (const float*)d_in[3];
    const float* ln1_s   = (const float*)d_in[4];
    const float* ln1_b   = (const float*)d_in[5];
    const float* qkv_w   = (const float*)d_in[6];
    const float* qkv_b   = (const float*)d_in[7];
    const float* proj_w  = (const float*)d_in[8];
    const float* proj_b  = (const float*)d_in[9];
    const float* ln2_s   = (const float*)d_in[10];
    const float* ln2_b   = (const float*)d_in[11];
    const float* fc1_w   = (const float*)d_in[12];
    const float* fc1_b   = (const float*)d_in[13];
    const float* fc2_w   = (const float*)d_in[14];
    const float* fc2_b   = (const float*)d_in[15];
    const float* lnf_s   = (const float*)d_in[16];
    const float* lnf_b   = (const float*)d_in[17];
    const float* head_w  = (const float*)d_in[18];
    float* out = (float*)d_out;

    float *X, *Hb, *QKV, *Y, *FF, *NLL;
    cudaGetSymbolAddress((void**)&X,   g_X);
    cudaGetSymbolAddress((void**)&Hb,  g_Hb);
    cudaGetSymbolAddress((void**)&QKV, g_QKV);
    cudaGetSymbolAddress((void**)&Y,   g_Y);
    cudaGetSymbolAddress((void**)&FF,  g_FF);
    cudaGetSymbolAddress((void**)&NLL, g_NLL);

    cudaFuncSetAttribute(attn_flash_k,
                         cudaFuncAttributeMaxDynamicSharedMemorySize, FLASH_SMEM);

    embed_k<<<MM, 256>>>(idx, tok_emb, pos_emb, X);

    for (int l = 0; l < NL; l++) {
        ln_w_k<<<MM / 8, 256>>>(X, ln1_s + (size_t)l * D, ln1_b + (size_t)l * D, Hb);
        gemm_tf32_k<1,0,0,0><<<dim3(3 * D / 128, MM / 128), 256>>>(
            Hb, qkv_w + (size_t)l * D * 3 * D, qkv_b + (size_t)l * 3 * D,
            nullptr, QKV, MM, 3 * D, D);
        attn_flash_k<<<dim3(TT / 64, BB * NH), 256, FLASH_SMEM>>>(QKV, Y);
        gemm_tf32_k<1,0,1,0><<<dim3(D / 128, MM / 128), 256>>>(
            Y, proj_w + (size_t)l * D * D, proj_b + (size_t)l * D,
            X, X, MM, D, D);
        ln_w_k<<<MM / 8, 256>>>(X, ln2_s + (size_t)l * D, ln2_b + (size_t)l * D, Hb);
        gemm_tf32_k<1,1,0,0><<<dim3(4 * D / 128, MM / 128), 256>>>(
            Hb, fc1_w + (size_t)l * D * 4 * D, fc1_b + (size_t)l * 4 * D,
            nullptr, FF, MM, 4 * D, D);
        gemm_tf32_k<1,0,1,0><<<dim3(D / 128, MM / 128), 256>>>(
            FF, fc2_w + (size_t)l * 4 * D * D, fc2_b + (size_t)l * D,
            X, X, MM, D, 4 * D);
    }

    ln_w_k<<<MM / 8, 256>>>(X, lnf_s, lnf_b, Hb);
    gemm_tf32_k<0,0,0,1><<<dim3(MM / 128, VOC / 128), 256>>>(
        Hb, head_w, nullptr, nullptr, out, MM, VOC, D);

    nll_k<<<MM, 256>>>(out, targets, NLL);
    loss_k<<<1, 256>>>(NLL, out + (size_t)out_size - 1);
}

// round 13
// speedup vs baseline: 1.0007x; 1.0007x over previous
#include <cuda_runtime.h>
#include <math.h>
#include <stdint.h>

#define NL  8
#define D   1024
#define NH  16
#define VOC 32000
#define TT  1024
#define BB  2
#define HDIM 64
#define MM  2048   // B*T

// ---------------- scratch (device globals; no allocations allowed) ----------
static __device__ float g_X  [(size_t)MM * D];
static __device__ float g_Hb [(size_t)MM * D];
static __device__ float g_QKV[(size_t)MM * 3 * D];
static __device__ float g_Y  [(size_t)MM * D];
static __device__ float g_FF [(size_t)MM * 4 * D];
static __device__ float g_NLL[(size_t)MM];

// ---------------- helpers -----------------------------------------------------
__device__ __forceinline__ uint32_t f2tf(float f) {
    uint32_t r;
    asm("cvt.rna.tf32.f32 %0, %1;" : "=r"(r) : "f"(f));
    return r;
}

__device__ __forceinline__ float blk_sum(float v, float* sh) {
    #pragma unroll
    for (int o = 16; o; o >>= 1) v += __shfl_xor_sync(0xffffffffu, v, o);
    if ((threadIdx.x & 31) == 0) sh[threadIdx.x >> 5] = v;
    __syncthreads();
    float r = 0.f;
    #pragma unroll
    for (int i = 0; i < 8; i++) r += sh[i];
    __syncthreads();
    return r;
}

__device__ __forceinline__ float blk_max(float v, float* sh) {
    #pragma unroll
    for (int o = 16; o; o >>= 1) v = fmaxf(v, __shfl_xor_sync(0xffffffffu, v, o));
    if ((threadIdx.x & 31) == 0) sh[threadIdx.x >> 5] = v;
    __syncthreads();
    float r = -1e30f;
    #pragma unroll
    for (int i = 0; i < 8; i++) r = fmaxf(r, sh[i]);
    __syncthreads();
    return r;
}

// ---------------- embedding --------------------------------------------------
__global__ void embed_k(const int* __restrict__ idx, const float* __restrict__ tok,
                        const float* __restrict__ pos, float* __restrict__ X) {
    const int r = blockIdx.x;
    const int t = r & (TT - 1);
    const int id = idx[r];
    const float* te = tok + (size_t)id * D;
    const float* pe = pos + (size_t)t * D;
    float* xr = X + (size_t)r * D;
    for (int c = threadIdx.x; c < D; c += 256)
        xr[c] = te[c] + pe[c];
}

// ---------------- layernorm: one warp per row, shfl-only ----------------------
__global__ void __launch_bounds__(256) ln_w_k(const float* __restrict__ X,
                                              const float* __restrict__ s,
                                              const float* __restrict__ b,
                                              float* __restrict__ O) {
    const int warp = threadIdx.x >> 5, lane = threadIdx.x & 31;
    const int r = (blockIdx.x << 3) + warp;
    const float* xr = X + (size_t)r * D;
    float4 xv[8];
    float sum = 0.f;
    #pragma unroll
    for (int j = 0; j < 8; j++) {
        xv[j] = *(const float4*)&xr[(j * 32 + lane) << 2];
        sum += xv[j].x + xv[j].y + xv[j].z + xv[j].w;
    }
    #pragma unroll
    for (int o = 16; o; o >>= 1) sum += __shfl_xor_sync(0xffffffffu, sum, o);
    const float mean = sum * (1.f / D);
    float var = 0.f;
    #pragma unroll
    for (int j = 0; j < 8; j++) {
        xv[j].x -= mean; xv[j].y -= mean; xv[j].z -= mean; xv[j].w -= mean;
        var += xv[j].x * xv[j].x + xv[j].y * xv[j].y
             + xv[j].z * xv[j].z + xv[j].w * xv[j].w;
    }
    #pragma unroll
    for (int o = 16; o; o >>= 1) var += __shfl_xor_sync(0xffffffffu, var, o);
    const float rinv = rsqrtf(var * (1.f / D) + 1e-5f);
    float* orow = O + (size_t)r * D;
    #pragma unroll
    for (int j = 0; j < 8; j++) {
        const int c = (j * 32 + lane) << 2;
        const float4 sv = *(const float4*)&s[c];
        const float4 bv = *(const float4*)&b[c];
        float4 o;
        o.x = xv[j].x * rinv * sv.x + bv.x;
        o.y = xv[j].y * rinv * sv.y + bv.y;
        o.z = xv[j].z * rinv * sv.z + bv.z;
        o.w = xv[j].w * rinv * sv.w + bv.w;
        *(float4*)&orow[c] = o;
    }
}

// ---------------- TF32 MMA macro ----------------------------------------------
#define MMA_TF32(d, a, b)                                                        \
    asm volatile(                                                                \
        "mma.sync.aligned.m16n8k8.row.col.f32.tf32.tf32.f32 "                    \
        "{%0,%1,%2,%3},{%4,%5,%6,%7},{%8,%9},{%0,%1,%2,%3};\n"                   \
        : "+f"(d[0]), "+f"(d[1]), "+f"(d[2]), "+f"(d[3])                         \
        : "r"(a[0]), "r"(a[1]), "r"(a[2]), "r"(a[3]), "r"(b[0]), "r"(b[1]))

// ---------------- TF32 tensor-core GEMM (double-buffered, 2 CTAs/SM) -----------
template<int DO_BIAS, int DO_GELU, int DO_RES, int SWAP>
__global__ void __launch_bounds__(256, 2) gemm_tf32_k(
    const float* __restrict__ A, const float* __restrict__ W,
    const float* __restrict__ bias, const float* __restrict__ res,
    float* __restrict__ C, int M, int N, int K)
{
    __shared__ uint32_t As[2][128][20];
    __shared__ uint32_t Bs[2][16][136];
    const int bm = (SWAP ? blockIdx.x : blockIdx.y) << 7;
    const int bn = (SWAP ? blockIdx.y : blockIdx.x) << 7;
    const int tid = threadIdx.x;
    const int warp = tid >> 5, lane = tid & 31;
    const int g = lane >> 2, t4 = lane & 3;
    const int wm = (warp >> 2) << 6;
    const int wn = (warp & 3) << 5;

    float acc[4][4][4];
    #pragma unroll
    for (int i = 0; i < 4; i++)
        #pragma unroll
        for (int j = 0; j < 4; j++)
            #pragma unroll
            for (int h = 0; h < 4; h++) acc[i][j][h] = 0.f;

    int a_r[2], a_c[2], b_r[2], b_c[2];
    #pragma unroll
    for (int i = 0; i < 2; i++) {
        const int idx = tid + (i << 8);
        a_r[i] = idx >> 2;  a_c[i] = (idx & 3) << 2;
        b_r[i] = idx >> 5;  b_c[i] = (idx & 31) << 2;
    }

    float4 pa[2], pb[2];
    #pragma unroll
    for (int i = 0; i < 2; i++) {
        pa[i] = *(const float4*)&A[(size_t)(bm + a_r[i]) * K + a_c[i]];
        pb[i] = *(const float4*)&W[(size_t)b_r[i] * N + bn + b_c[i]];
    }

    const int ntiles = K >> 4;
    for (int kt = 0; kt < ntiles; kt++) {
        const int buf = kt & 1;
        #pragma unroll
        for (int i = 0; i < 2; i++) {
            As[buf][a_r[i]][a_c[i] + 0] = f2tf(pa[i].x);
            As[buf][a_r[i]][a_c[i] + 1] = f2tf(pa[i].y);
            As[buf][a_r[i]][a_c[i] + 2] = f2tf(pa[i].z);
            As[buf][a_r[i]][a_c[i] + 3] = f2tf(pa[i].w);
            uint4 bw;
            bw.x = f2tf(pb[i].x); bw.y = f2tf(pb[i].y);
            bw.z = f2tf(pb[i].z); bw.w = f2tf(pb[i].w);
            *(uint4*)&Bs[buf][b_r[i]][b_c[i]] = bw;
        }
        __syncthreads();

        if (kt + 1 < ntiles) {
            const int k0 = (kt + 1) << 4;
            #pragma unroll
            for (int i = 0; i < 2; i++) {
                pa[i] = *(const float4*)&A[(size_t)(bm + a_r[i]) * K + k0 + a_c[i]];
                pb[i] = *(const float4*)&W[(size_t)(k0 + b_r[i]) * N + bn + b_c[i]];
            }
        }

        #pragma unroll
        for (int ks = 0; ks < 2; ks++) {
            const int kb = ks << 3;
            uint32_t af[4][4], bf[4][2];
            #pragma unroll
            for (int mt = 0; mt < 4; mt++) {
                const int m = wm + (mt << 4) + g;
                af[mt][0] = As[buf][m    ][kb + t4];
                af[mt][1] = As[buf][m + 8][kb + t4];
                af[mt][2] = As[buf][m    ][kb + t4 + 4];
                af[mt][3] = As[buf][m + 8][kb + t4 + 4];
            }
            #pragma unroll
            for (int nt = 0; nt < 4; nt++) {
                const int n = wn + (nt << 3) + g;
                bf[nt][0] = Bs[buf][kb + t4    ][n];
                bf[nt][1] = Bs[buf][kb + t4 + 4][n];
            }
            #pragma unroll
            for (int mt = 0; mt < 4; mt++)
                #pragma unroll
                for (int nt = 0; nt < 4; nt++)
                    MMA_TF32(acc[mt][nt], af[mt], bf[nt]);
        }
    }

    #pragma unroll
    for (int mt = 0; mt < 4; mt++) {
        #pragma unroll
        for (int nt = 0; nt < 4; nt++) {
            const int col = bn + wn + (nt << 3) + (t4 << 1);
            const float b0 = DO_BIAS ? bias[col]     : 0.f;
            const float b1 = DO_BIAS ? bias[col + 1] : 0.f;
            #pragma unroll
            for (int h = 0; h < 2; h++) {
                const int row = bm + wm + (mt << 4) + g + (h << 3);
                float v0 = acc[mt][nt][h * 2 + 0] + b0;
                float v1 = acc[mt][nt][h * 2 + 1] + b1;
                if (DO_GELU) {
                    v0 = 0.5f * v0 * (1.f + erff(v0 * 0.70710678118f));
                    v1 = 0.5f * v1 * (1.f + erff(v1 * 0.70710678118f));
                }
                const size_t off = (size_t)row * N + col;
                if (DO_RES) {
                    const float2 r = *(const float2*)&res[off];
                    v0 += r.x; v1 += r.y;
                }
                *(float2*)&C[off] = make_float2(v0, v1);
            }
        }
    }
}

// ---------------- fused flash attention (K/V register prefetch) ----------------
#define FLASH_SMEM (4 * 64 * 68 * 4 + 3 * 64 * 4)
__global__ void __launch_bounds__(256) attn_flash_k(const float* __restrict__ QKV,
                                                    float* __restrict__ Y) {
    extern __shared__ uint32_t dsm[];
    uint32_t (*Qs)[68] = (uint32_t(*)[68])dsm;
    uint32_t (*Ks)[68] = (uint32_t(*)[68])(dsm + 64 * 68);
    uint32_t (*Vs)[68] = (uint32_t(*)[68])(dsm + 2 * 64 * 68);
    uint32_t (*Ss)[68] = (uint32_t(*)[68])(dsm + 3 * 64 * 68);
    float* row_m     = (float*)(dsm + 4 * 64 * 68);
    float* row_l     = row_m + 64;
    float* row_scale = row_l + 64;

    const int q0 = blockIdx.x << 6;
    const int bh = blockIdx.y;
    const int b = bh >> 4, h = bh & 15;
    const int tid = threadIdx.x;
    const int warp = tid >> 5, lane = tid & 31;
    const int g = lane >> 2, t4 = lane & 3;
    const int wm = (warp >> 2) << 5;
    const int wn = (warp & 3) << 4;

    if (tid < 64) { row_m[tid] = -1e30f; row_l[tid] = 0.f; }

    int ld_r[4], ld_c[4];
    #pragma unroll
    for (int i = 0; i < 4; i++) {
        const int idx = tid + (i << 8);
        ld_r[i] = idx >> 4;
        ld_c[i] = (idx & 15) << 2;
    }

    #pragma unroll
    for (int i = 0; i < 4; i++) {
        const float4 qv = *(const float4*)&QKV[(size_t)(b * TT + q0 + ld_r[i]) * (3 * D) + h * HDIM + ld_c[i]];
        Qs[ld_r[i]][ld_c[i] + 0] = f2tf(qv.x); Qs[ld_r[i]][ld_c[i] + 1] = f2tf(qv.y);
        Qs[ld_r[i]][ld_c[i] + 2] = f2tf(qv.z); Qs[ld_r[i]][ld_c[i] + 3] = f2tf(qv.w);
    }

    float4 pk[4], pv[4];
    #pragma unroll
    for (int i = 0; i < 4; i++) {
        pk[i] = *(const float4*)&QKV[(size_t)(b * TT + ld_r[i]) * (3 * D) + D + h * HDIM + ld_c[i]];
        pv[i] = *(const float4*)&QKV[(size_t)(b * TT + ld_r[i]) * (3 * D) + 2 * D + h * HDIM + ld_c[i]];
    }

    float oacc[2][2][4];
    #pragma unroll
    for (int i = 0; i < 2; i++)
        #pragma unroll
        for (int j = 0; j < 2; j++)
            #pragma unroll
            for (int t = 0; t < 4; t++) oacc[i][j][t] = 0.f;

    for (int kt = 0; kt < 16; kt++) {
        #pragma unroll
        for (int i = 0; i < 4; i++) {
            Ks[ld_r[i]][ld_c[i] + 0] = f2tf(pk[i].x); Ks[ld_r[i]][ld_c[i] + 1] = f2tf(pk[i].y);
            Ks[ld_r[i]][ld_c[i] + 2] = f2tf(pk[i].z); Ks[ld_r[i]][ld_c[i] + 3] = f2tf(pk[i].w);
            Vs[ld_r[i]][ld_c[i] + 0] = f2tf(pv[i].x); Vs[ld_r[i]][ld_c[i] + 1] = f2tf(pv[i].y);
            Vs[ld_r[i]][ld_c[i] + 2] = f2tf(pv[i].z); Vs[ld_r[i]][ld_c[i] + 3] = f2tf(pv[i].w);
        }
        __syncthreads();

        if (kt + 1 < 16) {
            const int kn = (kt + 1) << 6;
            #pragma unroll
            for (int i = 0; i < 4; i++) {
                pk[i] = *(const float4*)&QKV[(size_t)(b * TT + kn + ld_r[i]) * (3 * D) + D + h * HDIM + ld_c[i]];
                pv[i] = *(const float4*)&QKV[(size_t)(b * TT + kn + ld_r[i]) * (3 * D) + 2 * D + h * HDIM + ld_c[i]];
            }
        }

        float sacc[2][2][4];
        #pragma unroll
        for (int i = 0; i < 2; i++)
            #pragma unroll
            for (int j = 0; j < 2; j++)
                #pragma unroll
                for (int t = 0; t < 4; t++) sacc[i][j][t] = 0.f;
        #pragma unroll
        for (int kb = 0; kb < 64; kb += 8) {
            uint32_t af[2][4], bf[2][2];
            #pragma unroll
            for (int mt = 0; mt < 2; mt++) {
                const int m = wm + (mt << 4) + g;
                af[mt][0] = Qs[m    ][kb + t4];
                af[mt][1] = Qs[m + 8][kb + t4];
                af[mt][2] = Qs[m    ][kb + t4 + 4];
                af[mt][3] = Qs[m + 8][kb + t4 + 4];
            }
            #pragma unroll
            for (int nt = 0; nt < 2; nt++) {
                const int n = wn + (nt << 3) + g;
                bf[nt][0] = Ks[n][kb + t4];
                bf[nt][1] = Ks[n][kb + t4 + 4];
            }
            #pragma unroll
            for (int mt = 0; mt < 2; mt++)
                #pragma unroll
                for (int nt = 0; nt < 2; nt++)
                    MMA_TF32(sacc[mt][nt], af[mt], bf[nt]);
        }
        #pragma unroll
        for (int mt = 0; mt < 2; mt++)
            #pragma unroll
            for (int nt = 0; nt < 2; nt++) {
                const int col = wn + (nt << 3) + (t4 << 1);
                #pragma unroll
                for (int hh = 0; hh < 2; hh++) {
                    const int row = wm + (mt << 4) + g + (hh << 3);
                    *(float2*)&Ss[row][col] = make_float2(sacc[mt][nt][hh * 2 + 0] * 0.125f,
                                                          sacc[mt][nt][hh * 2 + 1] * 0.125f);
                }
            }
        __syncthreads();

        {
            const int srow = tid >> 2, sq = tid & 3;
            float4 sv[4];
            float tmax = -1e30f;
            #pragma unroll
            for (int jj = 0; jj < 4; jj++) {
                sv[jj] = *(float4*)&Ss[srow][(sq << 4) + (jj << 2)];
                tmax = fmaxf(tmax, fmaxf(fmaxf(sv[jj].x, sv[jj].y), fmaxf(sv[jj].z, sv[jj].w)));
            }
            tmax = fmaxf(tmax, __shfl_xor_sync(0xffffffffu, tmax, 1));
            tmax = fmaxf(tmax, __shfl_xor_sync(0xffffffffu, tmax, 2));
            const float mo = row_m[srow];
            const float mn = fmaxf(mo, tmax);
            float tsum = 0.f;
            #pragma unroll
            for (int jj = 0; jj < 4; jj++) {
                sv[jj].x = __expf(sv[jj].x - mn); sv[jj].y = __expf(sv[jj].y - mn);
                sv[jj].z = __expf(sv[jj].z - mn); sv[jj].w = __expf(sv[jj].w - mn);
                tsum += sv[jj].x + sv[jj].y + sv[jj].z + sv[jj].w;
                uint4 u;
                u.x = f2tf(sv[jj].x); u.y = f2tf(sv[jj].y);
                u.z = f2tf(sv[jj].z); u.w = f2tf(sv[jj].w);
                *(uint4*)&Ss[srow][(sq << 4) + (jj << 2)] = u;
            }
            tsum += __shfl_xor_sync(0xffffffffu, tsum, 1);
            tsum += __shfl_xor_sync(0xffffffffu, tsum, 2);
            if (sq == 0) {
                const float sc = __expf(mo - mn);
                row_scale[srow] = sc;
                row_m[srow] = mn;
                row_l[srow] = row_l[srow] * sc + tsum;
            }
        }
        __syncthreads();

        #pragma unroll
        for (int mt = 0; mt < 2; mt++) {
            const float s0 = row_scale[wm + (mt << 4) + g];
            const float s1 = row_scale[wm + (mt << 4) + g + 8];
            #pragma unroll
            for (int nt = 0; nt < 2; nt++) {
                oacc[mt][nt][0] *= s0; oacc[mt][nt][1] *= s0;
                oacc[mt][nt][2] *= s1; oacc[mt][nt][3] *= s1;
            }
        }
        #pragma unroll
        for (int kb = 0; kb < 64; kb += 8) {
            uint32_t af[2][4], bf[2][2];
            #pragma unroll
            for (int mt = 0; mt < 2; mt++) {
                const int m = wm + (mt << 4) + g;
                af[mt][0] = Ss[m    ][kb + t4];
                af[mt][1] = Ss[m + 8][kb + t4];
                af[mt][2] = Ss[m    ][kb + t4 + 4];
                af[mt][3] = Ss[m + 8][kb + t4 + 4];
            }
            #pragma unroll
            for (int nt = 0; nt < 2; nt++) {
                const int n = wn + (nt << 3) + g;
                bf[nt][0] = Vs[kb + t4    ][n];
                bf[nt][1] = Vs[kb + t4 + 4][n];
            }
            #pragma unroll
            for (int mt = 0; mt < 2; mt++)
                #pragma unroll
                for (int nt = 0; nt < 2; nt++)
                    MMA_TF32(oacc[mt][nt], af[mt], bf[nt]);
        }
        __syncthreads();
    }

    #pragma unroll
    for (int mt = 0; mt < 2; mt++) {
        const float inv0 = 1.f / row_l[wm + (mt << 4) + g];
        const float inv1 = 1.f / row_l[wm + (mt << 4) + g + 8];
        #pragma unroll
        for (int nt = 0; nt < 2; nt++) {
            const int col = wn + (nt << 3) + (t4 << 1);
            const int row0 = q0 + wm + (mt << 4) + g;
            *(float2*)&Y[(size_t)(b * TT + row0) * D + h * HDIM + col] =
                make_float2(oacc[mt][nt][0] * inv0, oacc[mt][nt][1] * inv0);
            *(float2*)&Y[(size_t)(b * TT + row0 + 8) * D + h * HDIM + col] =
                make_float2(oacc[mt][nt][2] * inv1, oacc[mt][nt][3] * inv1);
        }
    }
}

// ---------------- loss ----------------------------------------------------------
__global__ void __launch_bounds__(256) nll_k(const float* __restrict__ logits,
                                             const int* __restrict__ tgt,
                                             float* __restrict__ nll) {
    __shared__ float sh[8];
    const int r = blockIdx.x;
    const float* row = logits + (size_t)r * VOC;
    float m = -1e30f;
    for (int c = threadIdx.x; c < VOC; c += 256) m = fmaxf(m, row[c]);
    m = blk_max(m, sh);
    float s = 0.f;
    for (int c = threadIdx.x; c < VOC; c += 256) s += __expf(row[c] - m);
    s = blk_sum(s, sh);
    if (threadIdx.x == 0) nll[r] = m + logf(s) - row[tgt[r]];
}

__global__ void __launch_bounds__(256) loss_k(const float* __restrict__ nll,
                                              float* __restrict__ out) {
    __shared__ float sh[8];
    float s = 0.f;
    for (int i = threadIdx.x; i < MM; i += 256) s += nll[i];
    s = blk_sum(s, sh);
    if (threadIdx.x == 0) out[0] = s * (1.f / MM);
}

// ---------------- orchestration --------------------------------------------------
extern "C" void kernel_launch(void* const* d_in, const int* in_sizes, int n_in,
                              void* d_out, int out_size) {
    const int*   idx     = (const int*)  d_in[0];
    const int*   targets = (const int*)  d_in[1];
    const float* tok_emb = (const float*)d_in[2];
    const float* pos_emb = (const float*)d_in[3];
    const float* ln1_s   = (const float*)d_in[4];
    const float* ln1_b   = (const float*)d_in[5];
    const float* qkv_w   = (const float*)d_in[6];
    const float* qkv_b   = (const float*)d_in[7];
    const float* proj_w  = (const float*)d_in[8];
    const float* proj_b  = (const float*)d_in[9];
    const float* ln2_s   = (const float*)d_in[10];
    const float* ln2_b   = (const float*)d_in[11];
    const float* fc1_w   = (const float*)d_in[12];
    const float* fc1_b   = (const float*)d_in[13];
    const float* fc2_w   = (const float*)d_in[14];
    const float* fc2_b   = (const float*)d_in[15];
    const float* lnf_s   = (const float*)d_in[16];
    const float* lnf_b   = (const float*)d_in[17];
    const float* head_w  = (const float*)d_in[18];
    float* out = (float*)d_out;

    float *X, *Hb, *QKV, *Y, *FF, *NLL;
    cudaGetSymbolAddress((void**)&X,   g_X);
    cudaGetSymbolAddress((void**)&Hb,  g_Hb);
    cudaGetSymbolAddress((void**)&QKV, g_QKV);
    cudaGetSymbolAddress((void**)&Y,   g_Y);
    cudaGetSymbolAddress((void**)&FF,  g_FF);
    cudaGetSymbolAddress((void**)&NLL, g_NLL);

    cudaFuncSetAttribute(attn_flash_k,
                         cudaFuncAttributeMaxDynamicSharedMemorySize, FLASH_SMEM);

    embed_k<<<MM, 256>>>(idx, tok_emb, pos_emb, X);

    for (int l = 0; l < NL; l++) {
        ln_w_k<<<MM / 8, 256>>>(X, ln1_s + (size_t)l * D, ln1_b + (size_t)l * D, Hb);
        gemm_tf32_k<1,0,0,0><<<dim3(3 * D / 128, MM / 128), 256>>>(
            Hb, qkv_w + (size_t)l * D * 3 * D, qkv_b + (size_t)l * 3 * D,
            nullptr, QKV, MM, 3 * D, D);
        attn_flash_k<<<dim3(TT / 64, BB * NH), 256, FLASH_SMEM>>>(QKV, Y);
        gemm_tf32_k<1,0,1,0><<<dim3(D / 128, MM / 128), 256>>>(
            Y, proj_w + (size_t)l * D * D, proj_b + (size_t)l * D,
            X, X, MM, D, D);
        ln_w_k<<<MM / 8, 256>>>(X, ln2_s + (size_t)l * D, ln2_b + (size_t)l * D, Hb);
        gemm_tf32_k<1,1,0,0><<<dim3(4 * D / 128, MM / 128), 256>>>(
            Hb, fc1_w + (size_t)l * D * 4 * D, fc1_b + (size_t)l * 4 * D,
            nullptr, FF, MM, 4 * D, D);
        gemm_tf32_k<1,0,1,0><<<dim3(D / 128, MM / 128), 256>>>(
            FF, fc2_w + (size_t)l * 4 * D * D, fc2_b + (size_t)l * D,
            X, X, MM, D, 4 * D);
    }

    ln_w_k<<<MM / 8, 256>>>(X, lnf_s, lnf_b, Hb);
    gemm_tf32_k<0,0,0,1><<<dim3(MM / 128, VOC / 128), 256>>>(
        Hb, head_w, nullptr, nullptr, out, MM, VOC, D);

    nll_k<<<MM, 256>>>(out, targets, NLL);
    loss_k<<<1, 256>>>(NLL, out + (size_t)out_size - 1);
}

// round 14
// speedup vs baseline: 1.0255x; 1.0248x over previous
#include <cuda_runtime.h>
#include <math.h>
#include <stdint.h>

#define NL  8
#define D   1024
#define NH  16
#define VOC 32000
#define TT  1024
#define BB  2
#define HDIM 64
#define MM  2048   // B*T

// ---------------- scratch (device globals; no allocations allowed) ----------
static __device__ float g_X  [(size_t)MM * D];
static __device__ float g_Hb [(size_t)MM * D];
static __device__ float g_QKV[(size_t)MM * 3 * D];
static __device__ float g_Y  [(size_t)MM * D];
static __device__ float g_FF [(size_t)MM * 4 * D];
static __device__ float g_NLL[(size_t)MM];

// ---------------- helpers -----------------------------------------------------
__device__ __forceinline__ uint32_t f2tf(float f) {
    uint32_t r;
    asm("cvt.rna.tf32.f32 %0, %1;" : "=r"(r) : "f"(f));
    return r;
}

__device__ __forceinline__ float blk_sum(float v, float* sh) {
    #pragma unroll
    for (int o = 16; o; o >>= 1) v += __shfl_xor_sync(0xffffffffu, v, o);
    if ((threadIdx.x & 31) == 0) sh[threadIdx.x >> 5] = v;
    __syncthreads();
    float r = 0.f;
    #pragma unroll
    for (int i = 0; i < 8; i++) r += sh[i];
    __syncthreads();
    return r;
}

__device__ __forceinline__ float blk_max(float v, float* sh) {
    #pragma unroll
    for (int o = 16; o; o >>= 1) v = fmaxf(v, __shfl_xor_sync(0xffffffffu, v, o));
    if ((threadIdx.x & 31) == 0) sh[threadIdx.x >> 5] = v;
    __syncthreads();
    float r = -1e30f;
    #pragma unroll
    for (int i = 0; i < 8; i++) r = fmaxf(r, sh[i]);
    __syncthreads();
    return r;
}

// ---------------- embedding --------------------------------------------------
__global__ void embed_k(const int* __restrict__ idx, const float* __restrict__ tok,
                        const float* __restrict__ pos, float* __restrict__ X) {
    const int r = blockIdx.x;
    const int t = r & (TT - 1);
    const int id = idx[r];
    const float* te = tok + (size_t)id * D;
    const float* pe = pos + (size_t)t * D;
    float* xr = X + (size_t)r * D;
    for (int c = threadIdx.x; c < D; c += 256)
        xr[c] = te[c] + pe[c];
}

// ---------------- layernorm: one warp per row, shfl-only ----------------------
__global__ void __launch_bounds__(256) ln_w_k(const float* __restrict__ X,
                                              const float* __restrict__ s,
                                              const float* __restrict__ b,
                                              float* __restrict__ O) {
    const int warp = threadIdx.x >> 5, lane = threadIdx.x & 31;
    const int r = (blockIdx.x << 3) + warp;
    const float* xr = X + (size_t)r * D;
    float4 xv[8];
    float sum = 0.f;
    #pragma unroll
    for (int j = 0; j < 8; j++) {
        xv[j] = *(const float4*)&xr[(j * 32 + lane) << 2];
        sum += xv[j].x + xv[j].y + xv[j].z + xv[j].w;
    }
    #pragma unroll
    for (int o = 16; o; o >>= 1) sum += __shfl_xor_sync(0xffffffffu, sum, o);
    const float mean = sum * (1.f / D);
    float var = 0.f;
    #pragma unroll
    for (int j = 0; j < 8; j++) {
        xv[j].x -= mean; xv[j].y -= mean; xv[j].z -= mean; xv[j].w -= mean;
        var += xv[j].x * xv[j].x + xv[j].y * xv[j].y
             + xv[j].z * xv[j].z + xv[j].w * xv[j].w;
    }
    #pragma unroll
    for (int o = 16; o; o >>= 1) var += __shfl_xor_sync(0xffffffffu, var, o);
    const float rinv = rsqrtf(var * (1.f / D) + 1e-5f);
    float* orow = O + (size_t)r * D;
    #pragma unroll
    for (int j = 0; j < 8; j++) {
        const int c = (j * 32 + lane) << 2;
        const float4 sv = *(const float4*)&s[c];
        const float4 bv = *(const float4*)&b[c];
        float4 o;
        o.x = xv[j].x * rinv * sv.x + bv.x;
        o.y = xv[j].y * rinv * sv.y + bv.y;
        o.z = xv[j].z * rinv * sv.z + bv.z;
        o.w = xv[j].w * rinv * sv.w + bv.w;
        *(float4*)&orow[c] = o;
    }
}

// ---------------- TF32 MMA macro ----------------------------------------------
#define MMA_TF32(d, a, b)                                                        \
    asm volatile(                                                                \
        "mma.sync.aligned.m16n8k8.row.col.f32.tf32.tf32.f32 "                    \
        "{%0,%1,%2,%3},{%4,%5,%6,%7},{%8,%9},{%0,%1,%2,%3};\n"                   \
        : "+f"(d[0]), "+f"(d[1]), "+f"(d[2]), "+f"(d[3])                         \
        : "r"(a[0]), "r"(a[1]), "r"(a[2]), "r"(a[3]), "r"(b[0]), "r"(b[1]))

// ---------------- TF32 GEMM: 4 warps, 64x64 warp tile, double-buffered ---------
// Halves fragment crossbar bytes per MMA vs the 8-warp 64x32 tiling.
template<int DO_BIAS, int DO_GELU, int DO_RES, int SWAP>
__global__ void __launch_bounds__(128) gemm_tf32_k(
    const float* __restrict__ A, const float* __restrict__ W,
    const float* __restrict__ bias, const float* __restrict__ res,
    float* __restrict__ C, int M, int N, int K)
{
    __shared__ uint32_t As[2][128][20];
    __shared__ uint32_t Bs[2][16][136];
    const int bm = (SWAP ? blockIdx.x : blockIdx.y) << 7;
    const int bn = (SWAP ? blockIdx.y : blockIdx.x) << 7;
    const int tid = threadIdx.x;
    const int warp = tid >> 5, lane = tid & 31;
    const int g = lane >> 2, t4 = lane & 3;
    const int wm = (warp >> 1) << 6;   // 0 / 64
    const int wn = (warp & 1) << 6;    // 0 / 64

    float acc[4][8][4];
    #pragma unroll
    for (int i = 0; i < 4; i++)
        #pragma unroll
        for (int j = 0; j < 8; j++)
            #pragma unroll
            for (int h = 0; h < 4; h++) acc[i][j][h] = 0.f;

    int a_r[4], a_c[4], b_r[4], b_c[4];
    #pragma unroll
    for (int i = 0; i < 4; i++) {
        const int idx = tid + (i << 7);
        a_r[i] = idx >> 2;  a_c[i] = (idx & 3) << 2;
        b_r[i] = idx >> 5;  b_c[i] = (idx & 31) << 2;
    }

    float4 pa[4], pb[4];
    #pragma unroll
    for (int i = 0; i < 4; i++) {
        pa[i] = *(const float4*)&A[(size_t)(bm + a_r[i]) * K + a_c[i]];
        pb[i] = *(const float4*)&W[(size_t)b_r[i] * N + bn + b_c[i]];
    }

    const int ntiles = K >> 4;
    for (int kt = 0; kt < ntiles; kt++) {
        const int buf = kt & 1;
        #pragma unroll
        for (int i = 0; i < 4; i++) {
            As[buf][a_r[i]][a_c[i] + 0] = f2tf(pa[i].x);
            As[buf][a_r[i]][a_c[i] + 1] = f2tf(pa[i].y);
            As[buf][a_r[i]][a_c[i] + 2] = f2tf(pa[i].z);
            As[buf][a_r[i]][a_c[i] + 3] = f2tf(pa[i].w);
            uint4 bw;
            bw.x = f2tf(pb[i].x); bw.y = f2tf(pb[i].y);
            bw.z = f2tf(pb[i].z); bw.w = f2tf(pb[i].w);
            *(uint4*)&Bs[buf][b_r[i]][b_c[i]] = bw;
        }
        __syncthreads();

        if (kt + 1 < ntiles) {
            const int k0 = (kt + 1) << 4;
            #pragma unroll
            for (int i = 0; i < 4; i++) {
                pa[i] = *(const float4*)&A[(size_t)(bm + a_r[i]) * K + k0 + a_c[i]];
                pb[i] = *(const float4*)&W[(size_t)(k0 + b_r[i]) * N + bn + b_c[i]];
            }
        }

        #pragma unroll
        for (int ks = 0; ks < 2; ks++) {
            const int kb = ks << 3;
            uint32_t af[4][4], bf[8][2];
            #pragma unroll
            for (int mt = 0; mt < 4; mt++) {
                const int m = wm + (mt << 4) + g;
                af[mt][0] = As[buf][m    ][kb + t4];
                af[mt][1] = As[buf][m + 8][kb + t4];
                af[mt][2] = As[buf][m    ][kb + t4 + 4];
                af[mt][3] = As[buf][m + 8][kb + t4 + 4];
            }
            #pragma unroll
            for (int nt = 0; nt < 8; nt++) {
                const int n = wn + (nt << 3) + g;
                bf[nt][0] = Bs[buf][kb + t4    ][n];
                bf[nt][1] = Bs[buf][kb + t4 + 4][n];
            }
            #pragma unroll
            for (int mt = 0; mt < 4; mt++)
                #pragma unroll
                for (int nt = 0; nt < 8; nt++)
                    MMA_TF32(acc[mt][nt], af[mt], bf[nt]);
        }
        __syncthreads();
    }

    #pragma unroll
    for (int mt = 0; mt < 4; mt++) {
        #pragma unroll
        for (int nt = 0; nt < 8; nt++) {
            const int col = bn + wn + (nt << 3) + (t4 << 1);
            const float b0 = DO_BIAS ? bias[col]     : 0.f;
            const float b1 = DO_BIAS ? bias[col + 1] : 0.f;
            #pragma unroll
            for (int h = 0; h < 2; h++) {
                const int row = bm + wm + (mt << 4) + g + (h << 3);
                float v0 = acc[mt][nt][h * 2 + 0] + b0;
                float v1 = acc[mt][nt][h * 2 + 1] + b1;
                if (DO_GELU) {
                    v0 = 0.5f * v0 * (1.f + erff(v0 * 0.70710678118f));
                    v1 = 0.5f * v1 * (1.f + erff(v1 * 0.70710678118f));
                }
                const size_t off = (size_t)row * N + col;
                if (DO_RES) {
                    const float2 r = *(const float2*)&res[off];
                    v0 += r.x; v1 += r.y;
                }
                *(float2*)&C[off] = make_float2(v0, v1);
            }
        }
    }
}

// ---------------- fused flash attention (K/V register prefetch) ----------------
#define FLASH_SMEM (4 * 64 * 68 * 4 + 3 * 64 * 4)
__global__ void __launch_bounds__(256) attn_flash_k(const float* __restrict__ QKV,
                                                    float* __restrict__ Y) {
    extern __shared__ uint32_t dsm[];
    uint32_t (*Qs)[68] = (uint32_t(*)[68])dsm;
    uint32_t (*Ks)[68] = (uint32_t(*)[68])(dsm + 64 * 68);
    uint32_t (*Vs)[68] = (uint32_t(*)[68])(dsm + 2 * 64 * 68);
    uint32_t (*Ss)[68] = (uint32_t(*)[68])(dsm + 3 * 64 * 68);
    float* row_m     = (float*)(dsm + 4 * 64 * 68);
    float* row_l     = row_m + 64;
    float* row_scale = row_l + 64;

    const int q0 = blockIdx.x << 6;
    const int bh = blockIdx.y;
    const int b = bh >> 4, h = bh & 15;
    const int tid = threadIdx.x;
    const int warp = tid >> 5, lane = tid & 31;
    const int g = lane >> 2, t4 = lane & 3;
    const int wm = (warp >> 2) << 5;
    const int wn = (warp & 3) << 4;

    if (tid < 64) { row_m[tid] = -1e30f; row_l[tid] = 0.f; }

    int ld_r[4], ld_c[4];
    #pragma unroll
    for (int i = 0; i < 4; i++) {
        const int idx = tid + (i << 8);
        ld_r[i] = idx >> 4;
        ld_c[i] = (idx & 15) << 2;
    }

    #pragma unroll
    for (int i = 0; i < 4; i++) {
        const float4 qv = *(const float4*)&QKV[(size_t)(b * TT + q0 + ld_r[i]) * (3 * D) + h * HDIM + ld_c[i]];
        Qs[ld_r[i]][ld_c[i] + 0] = f2tf(qv.x); Qs[ld_r[i]][ld_c[i] + 1] = f2tf(qv.y);
        Qs[ld_r[i]][ld_c[i] + 2] = f2tf(qv.z); Qs[ld_r[i]][ld_c[i] + 3] = f2tf(qv.w);
    }

    float4 pk[4], pv[4];
    #pragma unroll
    for (int i = 0; i < 4; i++) {
        pk[i] = *(const float4*)&QKV[(size_t)(b * TT + ld_r[i]) * (3 * D) + D + h * HDIM + ld_c[i]];
        pv[i] = *(const float4*)&QKV[(size_t)(b * TT + ld_r[i]) * (3 * D) + 2 * D + h * HDIM + ld_c[i]];
    }

    float oacc[2][2][4];
    #pragma unroll
    for (int i = 0; i < 2; i++)
        #pragma unroll
        for (int j = 0; j < 2; j++)
            #pragma unroll
            for (int t = 0; t < 4; t++) oacc[i][j][t] = 0.f;

    for (int kt = 0; kt < 16; kt++) {
        #pragma unroll
        for (int i = 0; i < 4; i++) {
            Ks[ld_r[i]][ld_c[i] + 0] = f2tf(pk[i].x); Ks[ld_r[i]][ld_c[i] + 1] = f2tf(pk[i].y);
            Ks[ld_r[i]][ld_c[i] + 2] = f2tf(pk[i].z); Ks[ld_r[i]][ld_c[i] + 3] = f2tf(pk[i].w);
            Vs[ld_r[i]][ld_c[i] + 0] = f2tf(pv[i].x); Vs[ld_r[i]][ld_c[i] + 1] = f2tf(pv[i].y);
            Vs[ld_r[i]][ld_c[i] + 2] = f2tf(pv[i].z); Vs[ld_r[i]][ld_c[i] + 3] = f2tf(pv[i].w);
        }
        __syncthreads();

        if (kt + 1 < 16) {
            const int kn = (kt + 1) << 6;
            #pragma unroll
            for (int i = 0; i < 4; i++) {
                pk[i] = *(const float4*)&QKV[(size_t)(b * TT + kn + ld_r[i]) * (3 * D) + D + h * HDIM + ld_c[i]];
                pv[i] = *(const float4*)&QKV[(size_t)(b * TT + kn + ld_r[i]) * (3 * D) + 2 * D + h * HDIM + ld_c[i]];
            }
        }

        float sacc[2][2][4];
        #pragma unroll
        for (int i = 0; i < 2; i++)
            #pragma unroll
            for (int j = 0; j < 2; j++)
                #pragma unroll
                for (int t = 0; t < 4; t++) sacc[i][j][t] = 0.f;
        #pragma unroll
        for (int kb = 0; kb < 64; kb += 8) {
            uint32_t af[2][4], bf[2][2];
            #pragma unroll
            for (int mt = 0; mt < 2; mt++) {
                const int m = wm + (mt << 4) + g;
                af[mt][0] = Qs[m    ][kb + t4];
                af[mt][1] = Qs[m + 8][kb + t4];
                af[mt][2] = Qs[m    ][kb + t4 + 4];
                af[mt][3] = Qs[m + 8][kb + t4 + 4];
            }
            #pragma unroll
            for (int nt = 0; nt < 2; nt++) {
                const int n = wn + (nt << 3) + g;
                bf[nt][0] = Ks[n][kb + t4];
                bf[nt][1] = Ks[n][kb + t4 + 4];
            }
            #pragma unroll
            for (int mt = 0; mt < 2; mt++)
                #pragma unroll
                for (int nt = 0; nt < 2; nt++)
                    MMA_TF32(sacc[mt][nt], af[mt], bf[nt]);
        }
        #pragma unroll
        for (int mt = 0; mt < 2; mt++)
            #pragma unroll
            for (int nt = 0; nt < 2; nt++) {
                const int col = wn + (nt << 3) + (t4 << 1);
                #pragma unroll
                for (int hh = 0; hh < 2; hh++) {
                    const int row = wm + (mt << 4) + g + (hh << 3);
                    *(float2*)&Ss[row][col] = make_float2(sacc[mt][nt][hh * 2 + 0] * 0.125f,
                                                          sacc[mt][nt][hh * 2 + 1] * 0.125f);
                }
            }
        __syncthreads();

        {
            const int srow = tid >> 2, sq = tid & 3;
            float4 sv[4];
            float tmax = -1e30f;
            #pragma unroll
            for (int jj = 0; jj < 4; jj++) {
                sv[jj] = *(float4*)&Ss[srow][(sq << 4) + (jj << 2)];
                tmax = fmaxf(tmax, fmaxf(fmaxf(sv[jj].x, sv[jj].y), fmaxf(sv[jj].z, sv[jj].w)));
            }
            tmax = fmaxf(tmax, __shfl_xor_sync(0xffffffffu, tmax, 1));
            tmax = fmaxf(tmax, __shfl_xor_sync(0xffffffffu, tmax, 2));
            const float mo = row_m[srow];
            const float mn = fmaxf(mo, tmax);
            float tsum = 0.f;
            #pragma unroll
            for (int jj = 0; jj < 4; jj++) {
                sv[jj].x = __expf(sv[jj].x - mn); sv[jj].y = __expf(sv[jj].y - mn);
                sv[jj].z = __expf(sv[jj].z - mn); sv[jj].w = __expf(sv[jj].w - mn);
                tsum += sv[jj].x + sv[jj].y + sv[jj].z + sv[jj].w;
                uint4 u;
                u.x = f2tf(sv[jj].x); u.y = f2tf(sv[jj].y);
                u.z = f2tf(sv[jj].z); u.w = f2tf(sv[jj].w);
                *(uint4*)&Ss[srow][(sq << 4) + (jj << 2)] = u;
            }
            tsum += __shfl_xor_sync(0xffffffffu, tsum, 1);
            tsum += __shfl_xor_sync(0xffffffffu, tsum, 2);
            if (sq == 0) {
                const float sc = __expf(mo - mn);
                row_scale[srow] = sc;
                row_m[srow] = mn;
                row_l[srow] = row_l[srow] * sc + tsum;
            }
        }
        __syncthreads();

        #pragma unroll
        for (int mt = 0; mt < 2; mt++) {
            const float s0 = row_scale[wm + (mt << 4) + g];
            const float s1 = row_scale[wm + (mt << 4) + g + 8];
            #pragma unroll
            for (int nt = 0; nt < 2; nt++) {
                oacc[mt][nt][0] *= s0; oacc[mt][nt][1] *= s0;
                oacc[mt][nt][2] *= s1; oacc[mt][nt][3] *= s1;
            }
        }
        #pragma unroll
        for (int kb = 0; kb < 64; kb += 8) {
            uint32_t af[2][4], bf[2][2];
            #pragma unroll
            for (int mt = 0; mt < 2; mt++) {
                const int m = wm + (mt << 4) + g;
                af[mt][0] = Ss[m    ][kb + t4];
                af[mt][1] = Ss[m + 8][kb + t4];
                af[mt][2] = Ss[m    ][kb + t4 + 4];
                af[mt][3] = Ss[m + 8][kb + t4 + 4];
            }
            #pragma unroll
            for (int nt = 0; nt < 2; nt++) {
                const int n = wn + (nt << 3) + g;
                bf[nt][0] = Vs[kb + t4    ][n];
                bf[nt][1] = Vs[kb + t4 + 4][n];
            }
            #pragma unroll
            for (int mt = 0; mt < 2; mt++)
                #pragma unroll
                for (int nt = 0; nt < 2; nt++)
                    MMA_TF32(oacc[mt][nt], af[mt], bf[nt]);
        }
        __syncthreads();
    }

    #pragma unroll
    for (int mt = 0; mt < 2; mt++) {
        const float inv0 = 1.f / row_l[wm + (mt << 4) + g];
        const float inv1 = 1.f / row_l[wm + (mt << 4) + g + 8];
        #pragma unroll
        for (int nt = 0; nt < 2; nt++) {
            const int col = wn + (nt << 3) + (t4 << 1);
            const int row0 = q0 + wm + (mt << 4) + g;
            *(float2*)&Y[(size_t)(b * TT + row0) * D + h * HDIM + col] =
                make_float2(oacc[mt][nt][0] * inv0, oacc[mt][nt][1] * inv0);
            *(float2*)&Y[(size_t)(b * TT + row0 + 8) * D + h * HDIM + col] =
                make_float2(oacc[mt][nt][2] * inv1, oacc[mt][nt][3] * inv1);
        }
    }
}

// ---------------- loss ----------------------------------------------------------
__global__ void __launch_bounds__(256) nll_k(const float* __restrict__ logits,
                                             const int* __restrict__ tgt,
                                             float* __restrict__ nll) {
    __shared__ float sh[8];
    const int r = blockIdx.x;
    const float* row = logits + (size_t)r * VOC;
    float m = -1e30f;
    for (int c = threadIdx.x; c < VOC; c += 256) m = fmaxf(m, row[c]);
    m = blk_max(m, sh);
    float s = 0.f;
    for (int c = threadIdx.x; c < VOC; c += 256) s += __expf(row[c] - m);
    s = blk_sum(s, sh);
    if (threadIdx.x == 0) nll[r] = m + logf(s) - row[tgt[r]];
}

__global__ void __launch_bounds__(256) loss_k(const float* __restrict__ nll,
                                              float* __restrict__ out) {
    __shared__ float sh[8];
    float s = 0.f;
    for (int i = threadIdx.x; i < MM; i += 256) s += nll[i];
    s = blk_sum(s, sh);
    if (threadIdx.x == 0) out[0] = s * (1.f / MM);
}

// ---------------- orchestration --------------------------------------------------
extern "C" void kernel_launch(void* const* d_in, const int* in_sizes, int n_in,
                              void* d_out, int out_size) {
    const int*   idx     = (const int*)  d_in[0];
    const int*   targets = (const int*)  d_in[1];
    const float* tok_emb = (const float*)d_in[2];
    const float* pos_emb = (const float*)d_in[3];
    const float* ln1_s   = (const float*)d_in[4];
    const float* ln1_b   = (const float*)d_in[5];
    const float* qkv_w   = (const float*)d_in[6];
    const float* qkv_b   = (const float*)d_in[7];
    const float* proj_w  = (const float*)d_in[8];
    const float* proj_b  = (const float*)d_in[9];
    const float* ln2_s   = (const float*)d_in[10];
    const float* ln2_b   = (const float*)d_in[11];
    const float* fc1_w   = (const float*)d_in[12];
    const float* fc1_b   = (const float*)d_in[13];
    const float* fc2_w   = (const float*)d_in[14];
    const float* fc2_b   = (const float*)d_in[15];
    const float* lnf_s   = (const float*)d_in[16];
    const float* lnf_b   = (const float*)d_in[17];
    const float* head_w  = (const float*)d_in[18];
    float* out = (float*)d_out;

    float *X, *Hb, *QKV, *Y, *FF, *NLL;
    cudaGetSymbolAddress((void**)&X,   g_X);
    cudaGetSymbolAddress((void**)&Hb,  g_Hb);
    cudaGetSymbolAddress((void**)&QKV, g_QKV);
    cudaGetSymbolAddress((void**)&Y,   g_Y);
    cudaGetSymbolAddress((void**)&FF,  g_FF);
    cudaGetSymbolAddress((void**)&NLL, g_NLL);

    cudaFuncSetAttribute(attn_flash_k,
                         cudaFuncAttributeMaxDynamicSharedMemorySize, FLASH_SMEM);

    embed_k<<<MM, 256>>>(idx, tok_emb, pos_emb, X);

    for (int l = 0; l < NL; l++) {
        ln_w_k<<<MM / 8, 256>>>(X, ln1_s + (size_t)l * D, ln1_b + (size_t)l * D, Hb);
        gemm_tf32_k<1,0,0,0><<<dim3(3 * D / 128, MM / 128), 128>>>(
            Hb, qkv_w + (size_t)l * D * 3 * D, qkv_b + (size_t)l * 3 * D,
            nullptr, QKV, MM, 3 * D, D);
        attn_flash_k<<<dim3(TT / 64, BB * NH), 256, FLASH_SMEM>>>(QKV, Y);
        gemm_tf32_k<1,0,1,0><<<dim3(D / 128, MM / 128), 128>>>(
            Y, proj_w + (size_t)l * D * D, proj_b + (size_t)l * D,
            X, X, MM, D, D);
        ln_w_k<<<MM / 8, 256>>>(X, ln2_s + (size_t)l * D, ln2_b + (size_t)l * D, Hb);
        gemm_tf32_k<1,1,0,0><<<dim3(4 * D / 128, MM / 128), 128>>>(
            Hb, fc1_w + (size_t)l * D * 4 * D, fc1_b + (size_t)l * 4 * D,
            nullptr, FF, MM, 4 * D, D);
        gemm_tf32_k<1,0,1,0><<<dim3(D / 128, MM / 128), 128>>>(
            FF, fc2_w + (size_t)l * 4 * D * D, fc2_b + (size_t)l * D,
            X, X, MM, D, 4 * D);
    }

    ln_w_k<<<MM / 8, 256>>>(X, lnf_s, lnf_b, Hb);
    gemm_tf32_k<0,0,0,1><<<dim3(MM / 128, VOC / 128), 128>>>(
        Hb, head_w, nullptr, nullptr, out, MM, VOC, D);

    nll_k<<<MM, 256>>>(out, targets, NLL);
    loss_k<<<1, 256>>>(NLL, out + (size_t)out_size - 1);
}

// round 17
// speedup vs baseline: 1.2299x; 1.1992x over previous
#include <cuda_runtime.h>
#include <cuda_fp16.h>
#include <math.h>
#include <stdint.h>

#define NL  8
#define D   1024
#define NH  16
#define VOC 32000
#define TT  1024
#define BB  2
#define HDIM 64
#define MM  2048

static __device__ float g_X  [(size_t)MM * D];
static __device__ float g_Hb [(size_t)MM * D];
static __device__ float g_QKV[(size_t)MM * 3 * D];
static __device__ float g_Y  [(size_t)MM * D];
static __device__ float g_FF [(size_t)MM * 4 * D];
static __device__ float g_NLL[(size_t)MM];

// ---------------- helpers -----------------------------------------------------
__device__ __forceinline__ uint32_t f2tf(float f) {
    uint32_t r; asm("cvt.rna.tf32.f32 %0, %1;" : "=r"(r) : "f"(f)); return r;
}
__device__ __forceinline__ uint32_t f2h2(float x, float y) {
    __half2 h = __floats2half2_rn(x, y);
    return *(uint32_t*)&h;
}
__device__ __forceinline__ float blk_sum(float v, float* sh) {
    #pragma unroll
    for (int o = 16; o; o >>= 1) v += __shfl_xor_sync(0xffffffffu, v, o);
    if ((threadIdx.x & 31) == 0) sh[threadIdx.x >> 5] = v;
    __syncthreads();
    float r = 0.f;
    #pragma unroll
    for (int i = 0; i < 8; i++) r += sh[i];
    __syncthreads();
    return r;
}
__device__ __forceinline__ float blk_max(float v, float* sh) {
    #pragma unroll
    for (int o = 16; o; o >>= 1) v = fmaxf(v, __shfl_xor_sync(0xffffffffu, v, o));
    if ((threadIdx.x & 31) == 0) sh[threadIdx.x >> 5] = v;
    __syncthreads();
    float r = -1e30f;
    #pragma unroll
    for (int i = 0; i < 8; i++) r = fmaxf(r, sh[i]);
    __syncthreads();
    return r;
}

// ---------------- embedding --------------------------------------------------
__global__ void embed_k(const int* __restrict__ idx, const float* __restrict__ tok,
                        const float* __restrict__ pos, float* __restrict__ X) {
    const int r = blockIdx.x, t = r & (TT - 1), id = idx[r];
    const float* te = tok + (size_t)id * D;
    const float* pe = pos + (size_t)t * D;
    float* xr = X + (size_t)r * D;
    for (int c = threadIdx.x; c < D; c += 256) xr[c] = te[c] + pe[c];
}

// ---------------- layernorm: one warp per row ----------------------------------
__global__ void __launch_bounds__(256) ln_w_k(const float* __restrict__ X,
                                              const float* __restrict__ s,
                                              const float* __restrict__ b,
                                              float* __restrict__ O) {
    const int warp = threadIdx.x >> 5, lane = threadIdx.x & 31;
    const int r = (blockIdx.x << 3) + warp;
    const float* xr = X + (size_t)r * D;
    float4 xv[8];
    float sum = 0.f;
    #pragma unroll
    for (int j = 0; j < 8; j++) {
        xv[j] = *(const float4*)&xr[(j * 32 + lane) << 2];
        sum += xv[j].x + xv[j].y + xv[j].z + xv[j].w;
    }
    #pragma unroll
    for (int o = 16; o; o >>= 1) sum += __shfl_xor_sync(0xffffffffu, sum, o);
    const float mean = sum * (1.f / D);
    float var = 0.f;
    #pragma unroll
    for (int j = 0; j < 8; j++) {
        xv[j].x -= mean; xv[j].y -= mean; xv[j].z -= mean; xv[j].w -= mean;
        var += xv[j].x*xv[j].x + xv[j].y*xv[j].y + xv[j].z*xv[j].z + xv[j].w*xv[j].w;
    }
    #pragma unroll
    for (int o = 16; o; o >>= 1) var += __shfl_xor_sync(0xffffffffu, var, o);
    const float rinv = rsqrtf(var * (1.f / D) + 1e-5f);
    float* orow = O + (size_t)r * D;
    #pragma unroll
    for (int j = 0; j < 8; j++) {
        const int c = (j * 32 + lane) << 2;
        const float4 sv = *(const float4*)&s[c];
        const float4 bv = *(const float4*)&b[c];
        float4 o;
        o.x = xv[j].x * rinv * sv.x + bv.x;
        o.y = xv[j].y * rinv * sv.y + bv.y;
        o.z = xv[j].z * rinv * sv.z + bv.z;
        o.w = xv[j].w * rinv * sv.w + bv.w;
        *(float4*)&orow[c] = o;
    }
}

// ---------------- MMA macros ----------------------------------------------------
#define MMA_TF32(d, a, b)                                                        \
    asm volatile(                                                                \
        "mma.sync.aligned.m16n8k8.row.col.f32.tf32.tf32.f32 "                    \
        "{%0,%1,%2,%3},{%4,%5,%6,%7},{%8,%9},{%0,%1,%2,%3};\n"                   \
        : "+f"(d[0]), "+f"(d[1]), "+f"(d[2]), "+f"(d[3])                         \
        : "r"(a[0]), "r"(a[1]), "r"(a[2]), "r"(a[3]), "r"(b[0]), "r"(b[1]))

#define MMA_F16(d, a, b)                                                         \
    asm volatile(                                                                \
        "mma.sync.aligned.m16n8k16.row.col.f32.f16.f16.f32 "                     \
        "{%0,%1,%2,%3},{%4,%5,%6,%7},{%8,%9},{%0,%1,%2,%3};\n"                   \
        : "+f"(d[0]), "+f"(d[1]), "+f"(d[2]), "+f"(d[3])                         \
        : "r"(a[0]), "r"(a[1]), "r"(a[2]), "r"(a[3]), "r"(b[0]), "r"(b[1]))

// ---------------- FP16 GEMM: 128x128x16 tiles, 4 warps (64x64), 2 stages -------
// A smem [m][kp] (kp = k/2, half2), pad 12; B smem [kp][n] half2 over k, pad 136.
// fp16 inputs have the same 10-bit mantissa as tf32 -> same rounding error,
// but m16n8k16 runs at 2x the tf32 FLOP rate and halves LDS traffic.
template<int DO_BIAS, int DO_GELU, int DO_RES, int SWAP>
__global__ void __launch_bounds__(128) gemm_f16_k(
    const float* __restrict__ A, const float* __restrict__ W,
    const float* __restrict__ bias, const float* __restrict__ res,
    float* __restrict__ C, int M, int N, int K)
{
    __shared__ uint32_t As[2][128][12];   // [m][kp0..7 + pad]
    __shared__ uint32_t Bs[2][8][136];    // [kp][n + pad]
    const int bm = (SWAP ? blockIdx.x : blockIdx.y) << 7;
    const int bn = (SWAP ? blockIdx.y : blockIdx.x) << 7;
    const int tid = threadIdx.x;
    const int warp = tid >> 5, lane = tid & 31;
    const int g = lane >> 2, t4 = lane & 3;
    const int wm = (warp >> 1) << 6;
    const int wn = (warp & 1) << 6;

    float acc[4][8][4];
    #pragma unroll
    for (int i = 0; i < 4; i++)
        #pragma unroll
        for (int j = 0; j < 8; j++)
            #pragma unroll
            for (int h = 0; h < 4; h++) acc[i][j][h] = 0.f;

    // A: 128 rows x 16 k = 512 float4; thread gets 4.
    int a_r[4], a_c[4];
    #pragma unroll
    for (int i = 0; i < 4; i++) {
        const int idx = tid + (i << 7);
        a_r[i] = idx >> 2;  a_c[i] = (idx & 3) << 2;   // k offset 0,4,8,12
    }
    // B: 8 kp x 128 n u32; thread stores 2 uint4 (needs 2 W rows each).
    int b_kp[2], b_n[2];
    #pragma unroll
    for (int i = 0; i < 2; i++) {
        const int idx = tid + (i << 7);
        b_kp[i] = idx >> 5;  b_n[i] = (idx & 31) << 2;
    }

    float4 pa[4], pb0[2], pb1[2];
    #pragma unroll
    for (int i = 0; i < 4; i++)
        pa[i] = *(const float4*)&A[(size_t)(bm + a_r[i]) * K + a_c[i]];
    #pragma unroll
    for (int i = 0; i < 2; i++) {
        pb0[i] = *(const float4*)&W[(size_t)(2 * b_kp[i]    ) * N + bn + b_n[i]];
        pb1[i] = *(const float4*)&W[(size_t)(2 * b_kp[i] + 1) * N + bn + b_n[i]];
    }

    const int ntiles = K >> 4;
    for (int kt = 0; kt < ntiles; kt++) {
        const int buf = kt & 1;
        #pragma unroll
        for (int i = 0; i < 4; i++) {
            const int kp = a_c[i] >> 1;
            As[buf][a_r[i]][kp    ] = f2h2(pa[i].x, pa[i].y);
            As[buf][a_r[i]][kp + 1] = f2h2(pa[i].z, pa[i].w);
        }
        #pragma unroll
        for (int i = 0; i < 2; i++) {
            uint4 w;
            w.x = f2h2(pb0[i].x, pb1[i].x);
            w.y = f2h2(pb0[i].y, pb1[i].y);
            w.z = f2h2(pb0[i].z, pb1[i].z);
            w.w = f2h2(pb0[i].w, pb1[i].w);
            *(uint4*)&Bs[buf][b_kp[i]][b_n[i]] = w;
        }
        __syncthreads();

        if (kt + 1 < ntiles) {
            const int k0 = (kt + 1) << 4;
            #pragma unroll
            for (int i = 0; i < 4; i++)
                pa[i] = *(const float4*)&A[(size_t)(bm + a_r[i]) * K + k0 + a_c[i]];
            #pragma unroll
            for (int i = 0; i < 2; i++) {
                pb0[i] = *(const float4*)&W[(size_t)(k0 + 2 * b_kp[i]    ) * N + bn + b_n[i]];
                pb1[i] = *(const float4*)&W[(size_t)(k0 + 2 * b_kp[i] + 1) * N + bn + b_n[i]];
            }
        }

        uint32_t af[4][4], bf[8][2];
        #pragma unroll
        for (int mt = 0; mt < 4; mt++) {
            const int m = wm + (mt << 4) + g;
            af[mt][0] = As[buf][m    ][t4];
            af[mt][1] = As[buf][m + 8][t4];
            af[mt][2] = As[buf][m    ][t4 + 4];
            af[mt][3] = As[buf][m + 8][t4 + 4];
        }
        #pragma unroll
        for (int nt = 0; nt < 8; nt++) {
            const int n = wn + (nt << 3) + g;
            bf[nt][0] = Bs[buf][t4    ][n];
            bf[nt][1] = Bs[buf][t4 + 4][n];
        }
        #pragma unroll
        for (int mt = 0; mt < 4; mt++)
            #pragma unroll
            for (int nt = 0; nt < 8; nt++)
                MMA_F16(acc[mt][nt], af[mt], bf[nt]);
        __syncthreads();
    }

    #pragma unroll
    for (int mt = 0; mt < 4; mt++) {
        #pragma unroll
        for (int nt = 0; nt < 8; nt++) {
            const int col = bn + wn + (nt << 3) + (t4 << 1);
            const float b0 = DO_BIAS ? bias[col]     : 0.f;
            const float b1 = DO_BIAS ? bias[col + 1] : 0.f;
            #pragma unroll
            for (int h = 0; h < 2; h++) {
                const int row = bm + wm + (mt << 4) + g + (h << 3);
                float v0 = acc[mt][nt][h * 2 + 0] + b0;
                float v1 = acc[mt][nt][h * 2 + 1] + b1;
                if (DO_GELU) {
                    v0 = 0.5f * v0 * (1.f + erff(v0 * 0.70710678118f));
                    v1 = 0.5f * v1 * (1.f + erff(v1 * 0.70710678118f));
                }
                const size_t off = (size_t)row * N + col;
                if (DO_RES) {
                    const float2 r = *(const float2*)&res[off];
                    v0 += r.x; v1 += r.y;
                }
                *(float2*)&C[off] = make_float2(v0, v1);
            }
        }
    }
}

// ---------------- fused flash attention (tf32, unchanged — proven) -------------
#define FLASH_SMEM (4 * 64 * 68 * 4 + 3 * 64 * 4)
__global__ void __launch_bounds__(256) attn_flash_k(const float* __restrict__ QKV,
                                                    float* __restrict__ Y) {
    extern __shared__ uint32_t dsm[];
    uint32_t (*Qs)[68] = (uint32_t(*)[68])dsm;
    uint32_t (*Ks)[68] = (uint32_t(*)[68])(dsm + 64 * 68);
    uint32_t (*Vs)[68] = (uint32_t(*)[68])(dsm + 2 * 64 * 68);
    uint32_t (*Ss)[68] = (uint32_t(*)[68])(dsm + 3 * 64 * 68);
    float* row_m = (float*)(dsm + 4 * 64 * 68);
    float* row_l = row_m + 64;
    float* row_scale = row_l + 64;
    const int q0 = blockIdx.x << 6;
    const int bh = blockIdx.y;
    const int b = bh >> 4, h = bh & 15;
    const int tid = threadIdx.x;
    const int warp = tid >> 5, lane = tid & 31;
    const int g = lane >> 2, t4 = lane & 3;
    const int wm = (warp >> 2) << 5;
    const int wn = (warp & 3) << 4;
    if (tid < 64) { row_m[tid] = -1e30f; row_l[tid] = 0.f; }
    int ld_r[4], ld_c[4];
    #pragma unroll
    for (int i = 0; i < 4; i++) {
        const int idx = tid + (i << 8);
        ld_r[i] = idx >> 4; ld_c[i] = (idx & 15) << 2;
    }
    #pragma unroll
    for (int i = 0; i < 4; i++) {
        const float4 qv = *(const float4*)&QKV[(size_t)(b * TT + q0 + ld_r[i]) * (3 * D) + h * HDIM + ld_c[i]];
        Qs[ld_r[i]][ld_c[i]+0]=f2tf(qv.x); Qs[ld_r[i]][ld_c[i]+1]=f2tf(qv.y);
        Qs[ld_r[i]][ld_c[i]+2]=f2tf(qv.z); Qs[ld_r[i]][ld_c[i]+3]=f2tf(qv.w);
    }
    float4 pk[4], pv[4];
    #pragma unroll
    for (int i = 0; i < 4; i++) {
        pk[i] = *(const float4*)&QKV[(size_t)(b * TT + ld_r[i]) * (3 * D) + D + h * HDIM + ld_c[i]];
        pv[i] = *(const float4*)&QKV[(size_t)(b * TT + ld_r[i]) * (3 * D) + 2 * D + h * HDIM + ld_c[i]];
    }
    float oacc[2][2][4];
    #pragma unroll
    for (int i = 0; i < 2; i++)
        #pragma unroll
        for (int j = 0; j < 2; j++)
            #pragma unroll
            for (int t = 0; t < 4; t++) oacc[i][j][t] = 0.f;
    for (int kt = 0; kt < 16; kt++) {
        #pragma unroll
        for (int i = 0; i < 4; i++) {
            Ks[ld_r[i]][ld_c[i]+0]=f2tf(pk[i].x); Ks[ld_r[i]][ld_c[i]+1]=f2tf(pk[i].y);
            Ks[ld_r[i]][ld_c[i]+2]=f2tf(pk[i].z); Ks[ld_r[i]][ld_c[i]+3]=f2tf(pk[i].w);
            Vs[ld_r[i]][ld_c[i]+0]=f2tf(pv[i].x); Vs[ld_r[i]][ld_c[i]+1]=f2tf(pv[i].y);
            Vs[ld_r[i]][ld_c[i]+2]=f2tf(pv[i].z); Vs[ld_r[i]][ld_c[i]+3]=f2tf(pv[i].w);
        }
        __syncthreads();
        if (kt + 1 < 16) {
            const int kn = (kt + 1) << 6;
            #pragma unroll
            for (int i = 0; i < 4; i++) {
                pk[i] = *(const float4*)&QKV[(size_t)(b * TT + kn + ld_r[i]) * (3 * D) + D + h * HDIM + ld_c[i]];
                pv[i] = *(const float4*)&QKV[(size_t)(b * TT + kn + ld_r[i]) * (3 * D) + 2 * D + h * HDIM + ld_c[i]];
            }
        }
        float sacc[2][2][4];
        #pragma unroll
        for (int i = 0; i < 2; i++)
            #pragma unroll
            for (int j = 0; j < 2; j++)
                #pragma unroll
                for (int t = 0; t < 4; t++) sacc[i][j][t] = 0.f;
        #pragma unroll
        for (int kb = 0; kb < 64; kb += 8) {
            uint32_t af[2][4], bf[2][2];
            #pragma unroll
            for (int mt = 0; mt < 2; mt++) {
                const int m = wm + (mt << 4) + g;
                af[mt][0] = Qs[m][kb+t4]; af[mt][1] = Qs[m+8][kb+t4];
                af[mt][2] = Qs[m][kb+t4+4]; af[mt][3] = Qs[m+8][kb+t4+4];
            }
            #pragma unroll
            for (int nt = 0; nt < 2; nt++) {
                const int n = wn + (nt << 3) + g;
                bf[nt][0] = Ks[n][kb+t4]; bf[nt][1] = Ks[n][kb+t4+4];
            }
            #pragma unroll
            for (int mt = 0; mt < 2; mt++)
                #pragma unroll
                for (int nt = 0; nt < 2; nt++)
                    MMA_TF32(sacc[mt][nt], af[mt], bf[nt]);
        }
        #pragma unroll
        for (int mt = 0; mt < 2; mt++)
            #pragma unroll
            for (int nt = 0; nt < 2; nt++) {
                const int col = wn + (nt << 3) + (t4 << 1);
                #pragma unroll
                for (int hh = 0; hh < 2; hh++) {
                    const int row = wm + (mt << 4) + g + (hh << 3);
                    *(float2*)&Ss[row][col] = make_float2(sacc[mt][nt][hh*2+0] * 0.125f,
                                                          sacc[mt][nt][hh*2+1] * 0.125f);
                }
            }
        __syncthreads();
        {
            const int srow = tid >> 2, sq = tid & 3;
            float4 sv[4];
            float tmax = -1e30f;
            #pragma unroll
            for (int jj = 0; jj < 4; jj++) {
                sv[jj] = *(float4*)&Ss[srow][(sq << 4) + (jj << 2)];
                tmax = fmaxf(tmax, fmaxf(fmaxf(sv[jj].x, sv[jj].y), fmaxf(sv[jj].z, sv[jj].w)));
            }
            tmax = fmaxf(tmax, __shfl_xor_sync(0xffffffffu, tmax, 1));
            tmax = fmaxf(tmax, __shfl_xor_sync(0xffffffffu, tmax, 2));
            const float mo = row_m[srow];
            const float mn = fmaxf(mo, tmax);
            float tsum = 0.f;
            #pragma unroll
            for (int jj = 0; jj < 4; jj++) {
                sv[jj].x = __expf(sv[jj].x - mn); sv[jj].y = __expf(sv[jj].y - mn);
                sv[jj].z = __expf(sv[jj].z - mn); sv[jj].w = __expf(sv[jj].w - mn);
                tsum += sv[jj].x + sv[jj].y + sv[jj].z + sv[jj].w;
                uint4 u;
                u.x = f2tf(sv[jj].x); u.y = f2tf(sv[jj].y);
                u.z = f2tf(sv[jj].z); u.w = f2tf(sv[jj].w);
                *(uint4*)&Ss[srow][(sq << 4) + (jj << 2)] = u;
            }
            tsum += __shfl_xor_sync(0xffffffffu, tsum, 1);
            tsum += __shfl_xor_sync(0xffffffffu, tsum, 2);
            if (sq == 0) {
                const float sc = __expf(mo - mn);
                row_scale[srow] = sc;
                row_m[srow] = mn;
                row_l[srow] = row_l[srow] * sc + tsum;
            }
        }
        __syncthreads();
        #pragma unroll
        for (int mt = 0; mt < 2; mt++) {
            const float s0 = row_scale[wm + (mt << 4) + g];
            const float s1 = row_scale[wm + (mt << 4) + g + 8];
            #pragma unroll
            for (int nt = 0; nt < 2; nt++) {
                oacc[mt][nt][0] *= s0; oacc[mt][nt][1] *= s0;
                oacc[mt][nt][2] *= s1; oacc[mt][nt][3] *= s1;
            }
        }
        #pragma unroll
        for (int kb = 0; kb < 64; kb += 8) {
            uint32_t af[2][4], bf[2][2];
            #pragma unroll
            for (int mt = 0; mt < 2; mt++) {
                const int m = wm + (mt << 4) + g;
                af[mt][0] = Ss[m][kb+t4]; af[mt][1] = Ss[m+8][kb+t4];
                af[mt][2] = Ss[m][kb+t4+4]; af[mt][3] = Ss[m+8][kb+t4+4];
            }
            #pragma unroll
            for (int nt = 0; nt < 2; nt++) {
                const int n = wn + (nt << 3) + g;
                bf[nt][0] = Vs[kb+t4][n]; bf[nt][1] = Vs[kb+t4+4][n];
            }
            #pragma unroll
            for (int mt = 0; mt < 2; mt++)
                #pragma unroll
                for (int nt = 0; nt < 2; nt++)
                    MMA_TF32(oacc[mt][nt], af[mt], bf[nt]);
        }
        __syncthreads();
    }
    #pragma unroll
    for (int mt = 0; mt < 2; mt++) {
        const float inv0 = 1.f / row_l[wm + (mt << 4) + g];
        const float inv1 = 1.f / row_l[wm + (mt << 4) + g + 8];
        #pragma unroll
        for (int nt = 0; nt < 2; nt++) {
            const int col = wn + (nt << 3) + (t4 << 1);
            const int row0 = q0 + wm + (mt << 4) + g;
            *(float2*)&Y[(size_t)(b * TT + row0) * D + h * HDIM + col] =
                make_float2(oacc[mt][nt][0] * inv0, oacc[mt][nt][1] * inv0);
            *(float2*)&Y[(size_t)(b * TT + row0 + 8) * D + h * HDIM + col] =
                make_float2(oacc[mt][nt][2] * inv1, oacc[mt][nt][3] * inv1);
        }
    }
}

// ---------------- loss ----------------------------------------------------------
__global__ void __launch_bounds__(256) nll_k(const float* __restrict__ logits,
                                             const int* __restrict__ tgt,
                                             float* __restrict__ nll) {
    __shared__ float sh[8];
    const int r = blockIdx.x;
    const float* row = logits + (size_t)r * VOC;
    float m = -1e30f;
    for (int c = threadIdx.x; c < VOC; c += 256) m = fmaxf(m, row[c]);
    m = blk_max(m, sh);
    float s = 0.f;
    for (int c = threadIdx.x; c < VOC; c += 256) s += __expf(row[c] - m);
    s = blk_sum(s, sh);
    if (threadIdx.x == 0) nll[r] = m + logf(s) - row[tgt[r]];
}
__global__ void __launch_bounds__(256) loss_k(const float* __restrict__ nll,
                                              float* __restrict__ out) {
    __shared__ float sh[8];
    float s = 0.f;
    for (int i = threadIdx.x; i < MM; i += 256) s += nll[i];
    s = blk_sum(s, sh);
    if (threadIdx.x == 0) out[0] = s * (1.f / MM);
}

// ---------------- orchestration --------------------------------------------------
extern "C" void kernel_launch(void* const* d_in, const int* in_sizes, int n_in,
                              void* d_out, int out_size) {
    const int*   idx     = (const int*)  d_in[0];
    const int*   targets = (const int*)  d_in[1];
    const float* tok_emb = (const float*)d_in[2];
    const float* pos_emb = (const float*)d_in[3];
    const float* ln1_s   = (const float*)d_in[4];
    const float* ln1_b   = (const float*)d_in[5];
    const float* qkv_w   = (const float*)d_in[6];
    const float* qkv_b   = (const float*)d_in[7];
    const float* proj_w  = (const float*)d_in[8];
    const float* proj_b  = (const float*)d_in[9];
    const float* ln2_s   = (const float*)d_in[10];
    const float* ln2_b   = (const float*)d_in[11];
    const float* fc1_w   = (const float*)d_in[12];
    const float* fc1_b   = (const float*)d_in[13];
    const float* fc2_w   = (const float*)d_in[14];
    const float* fc2_b   = (const float*)d_in[15];
    const float* lnf_s   = (const float*)d_in[16];
    const float* lnf_b   = (const float*)d_in[17];
    const float* head_w  = (const float*)d_in[18];
    float* out = (float*)d_out;

    float *X, *Hb, *QKV, *Y, *FF, *NLL;
    cudaGetSymbolAddress((void**)&X,   g_X);
    cudaGetSymbolAddress((void**)&Hb,  g_Hb);
    cudaGetSymbolAddress((void**)&QKV, g_QKV);
    cudaGetSymbolAddress((void**)&Y,   g_Y);
    cudaGetSymbolAddress((void**)&FF,  g_FF);
    cudaGetSymbolAddress((void**)&NLL, g_NLL);

    cudaFuncSetAttribute(attn_flash_k,
                         cudaFuncAttributeMaxDynamicSharedMemorySize, FLASH_SMEM);

    embed_k<<<MM, 256>>>(idx, tok_emb, pos_emb, X);

    for (int l = 0; l < NL; l++) {
        ln_w_k<<<MM / 8, 256>>>(X, ln1_s + (size_t)l * D, ln1_b + (size_t)l * D, Hb);
        gemm_f16_k<1,0,0,0><<<dim3(3 * D / 128, MM / 128), 128>>>(
            Hb, qkv_w + (size_t)l * D * 3 * D, qkv_b + (size_t)l * 3 * D,
            nullptr, QKV, MM, 3 * D, D);
        attn_flash_k<<<dim3(TT / 64, BB * NH), 256, FLASH_SMEM>>>(QKV, Y);
        gemm_f16_k<1,0,1,0><<<dim3(D / 128, MM / 128), 128>>>(
            Y, proj_w + (size_t)l * D * D, proj_b + (size_t)l * D,
            X, X, MM, D, D);
        ln_w_k<<<MM / 8, 256>>>(X, ln2_s + (size_t)l * D, ln2_b + (size_t)l * D, Hb);
        gemm_f16_k<1,1,0,0><<<dim3(4 * D / 128, MM / 128), 128>>>(
            Hb, fc1_w + (size_t)l * D * 4 * D, fc1_b + (size_t)l * 4 * D,
            nullptr, FF, MM, 4 * D, D);
        gemm_f16_k<1,0,1,0><<<dim3(D / 128, MM / 128), 128>>>(
            FF, fc2_w + (size_t)l * 4 * D * D, fc2_b + (size_t)l * D,
            X, X, MM, D, 4 * D);
    }

    ln_w_k<<<MM / 8, 256>>>(X, lnf_s, lnf_b, Hb);
    gemm_f16_k<0,0,0,1><<<dim3(MM / 128, VOC / 128), 128>>>(
        Hb, head_w, nullptr, nullptr, out, MM, VOC, D);

    nll_k<<<MM, 256>>>(out, targets, NLL);
    loss_k<<<1, 256>>>(NLL, out + (size_t)out_size - 1);
}